// round 1
// baseline (speedup 1.0000x reference)
#include <cuda_runtime.h>
#include <math_constants.h>
#include <cstdint>

#define B_   2
#define T_   2048
#define EMB_ 2048
#define H_   16
#define HD_  128
#define M_   (B_ * T_)   // 4096

// Scratch (allocation-free rule: __device__ globals)
__device__ float g_q[(size_t)B_ * T_ * EMB_];
__device__ float g_k[(size_t)B_ * T_ * EMB_];
__device__ float g_v[(size_t)B_ * T_ * EMB_];
__device__ float g_attn[(size_t)B_ * T_ * EMB_];

// ---------------------------------------------------------------------------
// SGEMM: C[m,n] = sum_k A[m,k] * W[n,k]   (A row-major MxK, W row-major NxK)
// 128x128 block, BK=8, 256 threads, 8x8 per thread.
// ---------------------------------------------------------------------------
__global__ __launch_bounds__(256, 2)
void sgemm_abt(const float* __restrict__ A, const float* __restrict__ W,
               float* __restrict__ C, int M, int N, int K) {
    __shared__ float As[8][128];
    __shared__ float Bs[8][128];
    const int tid = threadIdx.x;
    const int m0 = blockIdx.y * 128;
    const int n0 = blockIdx.x * 128;
    const int tx = tid & 15;
    const int ty = tid >> 4;
    const int lrow = tid >> 1;
    const int lk = (tid & 1) * 4;

    const float* Ap = A + (size_t)(m0 + lrow) * K + lk;
    const float* Wp = W + (size_t)(n0 + lrow) * K + lk;

    float acc[8][8];
#pragma unroll
    for (int i = 0; i < 8; i++)
#pragma unroll
        for (int j = 0; j < 8; j++) acc[i][j] = 0.f;

    for (int k0 = 0; k0 < K; k0 += 8) {
        float4 av = *(const float4*)(Ap + k0);
        float4 wv = *(const float4*)(Wp + k0);
        __syncthreads();
        As[lk + 0][lrow] = av.x; As[lk + 1][lrow] = av.y;
        As[lk + 2][lrow] = av.z; As[lk + 3][lrow] = av.w;
        Bs[lk + 0][lrow] = wv.x; Bs[lk + 1][lrow] = wv.y;
        Bs[lk + 2][lrow] = wv.z; Bs[lk + 3][lrow] = wv.w;
        __syncthreads();
#pragma unroll
        for (int kk = 0; kk < 8; kk++) {
            float a[8], b[8];
            *(float4*)(a)     = *(const float4*)&As[kk][ty * 8];
            *(float4*)(a + 4) = *(const float4*)&As[kk][ty * 8 + 4];
            *(float4*)(b)     = *(const float4*)&Bs[kk][tx * 8];
            *(float4*)(b + 4) = *(const float4*)&Bs[kk][tx * 8 + 4];
#pragma unroll
            for (int i = 0; i < 8; i++)
#pragma unroll
                for (int j = 0; j < 8; j++)
                    acc[i][j] += a[i] * b[j];
        }
    }
#pragma unroll
    for (int i = 0; i < 8; i++) {
        float* Cp = C + (size_t)(m0 + ty * 8 + i) * N + n0 + tx * 8;
        *(float4*)(Cp)     = make_float4(acc[i][0], acc[i][1], acc[i][2], acc[i][3]);
        *(float4*)(Cp + 4) = make_float4(acc[i][4], acc[i][5], acc[i][6], acc[i][7]);
    }
}

// ---------------------------------------------------------------------------
// RoPE (interleaved pairs) applied in place to g_q and g_k.
// idx = ((b*T + t)*H + h)*64 + i2
// ---------------------------------------------------------------------------
__global__ void rope_kernel(float* __restrict__ q, float* __restrict__ k,
                            const float* __restrict__ cosv,
                            const float* __restrict__ sinv) {
    int idx = blockIdx.x * blockDim.x + threadIdx.x;
    if (idx >= B_ * T_ * H_ * (HD_ / 2)) return;
    int i2 = idx & 63;
    int bt = idx >> 10;            // b*T + t
    int t = bt & (T_ - 1);
    float c = cosv[t * 64 + i2];
    float s = sinv[t * 64 + i2];
    size_t base = (size_t)idx * 2;

    float xr = q[base], xi = q[base + 1];
    q[base]     = xr * c - xi * s;
    q[base + 1] = xr * s + xi * c;

    xr = k[base]; xi = k[base + 1];
    k[base]     = xr * c - xi * s;
    k[base + 1] = xr * s + xi * c;
}

// ---------------------------------------------------------------------------
// Flash attention, fp32, no mask (all 2048 keys per query).
// Block: 64 q-rows, 8 warps, each warp owns 8 rows.
// K tile stored k-major Ks[d][c] (pad 65) for conflict-free S compute.
// Online softmax; PV via shfl broadcast of probabilities.
// Dynamic smem: Qs(64*128) + Vs(64*128) + Ks(128*65) floats = 98816 bytes.
// ---------------------------------------------------------------------------
#define ATTN_SMEM_BYTES ((64 * 128 + 64 * 128 + 128 * 65) * 4)

__global__ __launch_bounds__(256, 2)
void attn_kernel(const float* __restrict__ Q, const float* __restrict__ Kg,
                 const float* __restrict__ Vg, float* __restrict__ Og) {
    extern __shared__ float sm[];
    float* Qs = sm;                    // [64][128]
    float* Vs = sm + 64 * 128;         // [64][128]
    float* Ks = sm + 2 * 64 * 128;     // [128][65] (k-major, padded)

    const int tid = threadIdx.x;
    const int lane = tid & 31;
    const int warp = tid >> 5;
    const int t0 = blockIdx.x * 64;
    const int h = blockIdx.y;
    const int b = blockIdx.z;
    const size_t headoff = ((size_t)b * T_ * H_ + h) * HD_;

    // Load Q tile (64 rows x 128)
    {
        const float* qbase = Q + headoff + (size_t)t0 * EMB_;
#pragma unroll
        for (int i = 0; i < 8; i++) {
            int f = tid + 256 * i;     // float4 index 0..2047
            int r = f >> 5, d4 = f & 31;
            float4 v = *(const float4*)(qbase + (size_t)r * EMB_ + d4 * 4);
            *(float4*)&Qs[r * 128 + d4 * 4] = v;
        }
    }

    float m_s[8], l_s[8], acc[8][4];
#pragma unroll
    for (int r = 0; r < 8; r++) {
        m_s[r] = -CUDART_INF_F;
        l_s[r] = 0.f;
#pragma unroll
        for (int d = 0; d < 4; d++) acc[r][d] = 0.f;
    }
    const float scale = 0.08838834764831845f;  // 1/sqrt(128)

    for (int n0 = 0; n0 < T_; n0 += 64) {
        const float* kbase = Kg + headoff + (size_t)n0 * EMB_;
        const float* vbase = Vg + headoff + (size_t)n0 * EMB_;
        __syncthreads();
#pragma unroll
        for (int i = 0; i < 8; i++) {
            int f = tid + 256 * i;
            int r = f >> 5, d4 = f & 31;
            float4 kv = *(const float4*)(kbase + (size_t)r * EMB_ + d4 * 4);
            Ks[(d4 * 4 + 0) * 65 + r] = kv.x;
            Ks[(d4 * 4 + 1) * 65 + r] = kv.y;
            Ks[(d4 * 4 + 2) * 65 + r] = kv.z;
            Ks[(d4 * 4 + 3) * 65 + r] = kv.w;
            float4 vv = *(const float4*)(vbase + (size_t)r * EMB_ + d4 * 4);
            *(float4*)&Vs[r * 128 + d4 * 4] = vv;
        }
        __syncthreads();

        // ---- S = Q K^T for this warp's 8 rows; lane owns cols lane, lane+32
        float s0[8], s1[8];
#pragma unroll
        for (int r = 0; r < 8; r++) { s0[r] = 0.f; s1[r] = 0.f; }
#pragma unroll 8
        for (int k4 = 0; k4 < 32; k4++) {
            float kv0[4], kv1[4];
#pragma unroll
            for (int j = 0; j < 4; j++) {
                kv0[j] = Ks[(k4 * 4 + j) * 65 + lane];
                kv1[j] = Ks[(k4 * 4 + j) * 65 + 32 + lane];
            }
#pragma unroll
            for (int r = 0; r < 8; r++) {
                float4 q4 = *(const float4*)&Qs[(warp * 8 + r) * 128 + k4 * 4];
                s0[r] += q4.x * kv0[0] + q4.y * kv0[1] + q4.z * kv0[2] + q4.w * kv0[3];
                s1[r] += q4.x * kv1[0] + q4.y * kv1[1] + q4.z * kv1[2] + q4.w * kv1[3];
            }
        }

        // ---- online softmax per row
        float ps0[8], ps1[8];
#pragma unroll
        for (int r = 0; r < 8; r++) {
            float a0 = s0[r] * scale;
            float a1 = s1[r] * scale;
            float mt = fmaxf(a0, a1);
#pragma unroll
            for (int off = 16; off; off >>= 1)
                mt = fmaxf(mt, __shfl_xor_sync(0xffffffffu, mt, off));
            float mnew = fmaxf(m_s[r], mt);
            float alpha = __expf(m_s[r] - mnew);
            float p0 = __expf(a0 - mnew);
            float p1 = __expf(a1 - mnew);
            float rs = p0 + p1;
#pragma unroll
            for (int off = 16; off; off >>= 1)
                rs += __shfl_xor_sync(0xffffffffu, rs, off);
            l_s[r] = l_s[r] * alpha + rs;
            m_s[r] = mnew;
#pragma unroll
            for (int d = 0; d < 4; d++) acc[r][d] *= alpha;
            ps0[r] = p0;
            ps1[r] = p1;
        }

        // ---- O += P * V
#pragma unroll
        for (int chunk = 0; chunk < 2; chunk++) {
#pragma unroll 8
            for (int ls = 0; ls < 32; ls++) {
                int c = chunk * 32 + ls;
                float v0 = Vs[c * 128 + lane];
                float v1 = Vs[c * 128 + 32 + lane];
                float v2 = Vs[c * 128 + 64 + lane];
                float v3 = Vs[c * 128 + 96 + lane];
#pragma unroll
                for (int r = 0; r < 8; r++) {
                    float pb = __shfl_sync(0xffffffffu,
                                           chunk ? ps1[r] : ps0[r], ls);
                    acc[r][0] += pb * v0;
                    acc[r][1] += pb * v1;
                    acc[r][2] += pb * v2;
                    acc[r][3] += pb * v3;
                }
            }
        }
    }

    // ---- epilogue: normalize and write to g_attn (layout [B,T,H*HD])
#pragma unroll
    for (int r = 0; r < 8; r++) {
        int row = warp * 8 + r;
        float inv = 1.f / l_s[r];
        float* ob = Og + headoff + (size_t)(t0 + row) * EMB_;
        ob[lane]      = acc[r][0] * inv;
        ob[32 + lane] = acc[r][1] * inv;
        ob[64 + lane] = acc[r][2] * inv;
        ob[96 + lane] = acc[r][3] * inv;
    }
}

// ---------------------------------------------------------------------------
extern "C" void kernel_launch(void* const* d_in, const int* in_sizes, int n_in,
                              void* d_out, int out_size) {
    const float* x    = (const float*)d_in[0];
    const float* wq   = (const float*)d_in[1];
    const float* wk   = (const float*)d_in[2];
    const float* wv   = (const float*)d_in[3];
    const float* wo   = (const float*)d_in[4];
    // d_in[5] k_cache, d_in[6] v_cache: zero, start_pos=0, not part of output.
    const float* fcos = (const float*)d_in[7];
    const float* fsin = (const float*)d_in[8];
    float* out = (float*)d_out;

    float *gq, *gk, *gv, *gattn;
    cudaGetSymbolAddress((void**)&gq, g_q);
    cudaGetSymbolAddress((void**)&gk, g_k);
    cudaGetSymbolAddress((void**)&gv, g_v);
    cudaGetSymbolAddress((void**)&gattn, g_attn);

    cudaFuncSetAttribute(attn_kernel,
                         cudaFuncAttributeMaxDynamicSharedMemorySize,
                         ATTN_SMEM_BYTES);

    dim3 ggrid(EMB_ / 128, M_ / 128);
    sgemm_abt<<<ggrid, 256>>>(x, wq, gq, M_, EMB_, EMB_);
    sgemm_abt<<<ggrid, 256>>>(x, wk, gk, M_, EMB_, EMB_);
    sgemm_abt<<<ggrid, 256>>>(x, wv, gv, M_, EMB_, EMB_);

    int nrope = B_ * T_ * H_ * (HD_ / 2);
    rope_kernel<<<(nrope + 255) / 256, 256>>>(gq, gk, fcos, fsin);

    dim3 agrid(T_ / 64, H_, B_);
    attn_kernel<<<agrid, 256, ATTN_SMEM_BYTES>>>(gq, gk, gv, gattn);

    sgemm_abt<<<ggrid, 256>>>(gattn, wo, out, M_, EMB_, EMB_);
}

// round 6
// speedup vs baseline: 1.6003x; 1.6003x over previous
#include <cuda_runtime.h>
#include <cuda_bf16.h>
#include <math_constants.h>
#include <cstdint>

#define B_   2
#define T_   2048
#define EMB_ 2048
#define H_   16
#define HD_  128
#define M_   (B_ * T_)   // 4096

// ---------------------------------------------------------------------------
// Scratch (__device__ globals; no allocation allowed)
// ---------------------------------------------------------------------------
__device__ float g_q[(size_t)M_ * EMB_];
__device__ float g_k[(size_t)M_ * EMB_];
__device__ float g_v[(size_t)M_ * EMB_];
__device__ float g_attn[(size_t)M_ * EMB_];
__device__ __nv_bfloat16 g_xh[(size_t)M_ * EMB_];
__device__ __nv_bfloat16 g_xl[(size_t)M_ * EMB_];
__device__ __nv_bfloat16 g_wh[4][(size_t)EMB_ * EMB_];
__device__ __nv_bfloat16 g_wl[4][(size_t)EMB_ * EMB_];
__device__ __nv_bfloat16 g_ah[(size_t)M_ * EMB_];
__device__ __nv_bfloat16 g_al[(size_t)M_ * EMB_];

// ---------------------------------------------------------------------------
// helpers
// ---------------------------------------------------------------------------
__device__ __forceinline__ uint32_t smem_u32(const void* p) {
    uint32_t a;
    asm("{ .reg .u64 t; cvta.to.shared.u64 t, %1; cvt.u32.u64 %0, t; }"
        : "=r"(a) : "l"(p));
    return a;
}
#define CP16(dst, src) \
    asm volatile("cp.async.cg.shared.global [%0], [%1], 16;" \
                 :: "r"(dst), "l"(src))
#define CP_COMMIT() asm volatile("cp.async.commit_group;" ::: "memory")
#define CP_WAIT(n)  asm volatile("cp.async.wait_group %0;" :: "n"(n) : "memory")

#define LDM_X4(r0, r1, r2, r3, addr)                                          \
    asm volatile("ldmatrix.sync.aligned.m8n8.x4.shared.b16 {%0,%1,%2,%3}, [%4];" \
                 : "=r"(r0), "=r"(r1), "=r"(r2), "=r"(r3) : "r"(addr))

#define MMA_BF16(d, a, b)                                                     \
    asm volatile("mma.sync.aligned.m16n8k16.row.col.f32.bf16.bf16.f32 "       \
                 "{%0,%1,%2,%3}, {%4,%5,%6,%7}, {%8,%9}, {%0,%1,%2,%3};"      \
                 : "+f"((d)[0]), "+f"((d)[1]), "+f"((d)[2]), "+f"((d)[3])     \
                 : "r"((a)[0]), "r"((a)[1]), "r"((a)[2]), "r"((a)[3]),        \
                   "r"((b)[0]), "r"((b)[1]))

// ---------------------------------------------------------------------------
// fp32 -> bf16 hi/lo split
// ---------------------------------------------------------------------------
__global__ void cvt_hilo(const float* __restrict__ src,
                         __nv_bfloat16* __restrict__ hi,
                         __nv_bfloat16* __restrict__ lo, int n4) {
    int i = blockIdx.x * blockDim.x + threadIdx.x;
    if (i >= n4) return;
    float4 v = ((const float4*)src)[i];
    __nv_bfloat16 h0 = __float2bfloat16(v.x);
    __nv_bfloat16 h1 = __float2bfloat16(v.y);
    __nv_bfloat16 h2 = __float2bfloat16(v.z);
    __nv_bfloat16 h3 = __float2bfloat16(v.w);
    __nv_bfloat16 l0 = __float2bfloat16(v.x - __bfloat162float(h0));
    __nv_bfloat16 l1 = __float2bfloat16(v.y - __bfloat162float(h1));
    __nv_bfloat16 l2 = __float2bfloat16(v.z - __bfloat162float(h2));
    __nv_bfloat16 l3 = __float2bfloat16(v.w - __bfloat162float(h3));
    ((__nv_bfloat162*)hi)[2 * i]     = __nv_bfloat162(h0, h1);
    ((__nv_bfloat162*)hi)[2 * i + 1] = __nv_bfloat162(h2, h3);
    ((__nv_bfloat162*)lo)[2 * i]     = __nv_bfloat162(l0, l1);
    ((__nv_bfloat162*)lo)[2 * i + 1] = __nv_bfloat162(l2, l3);
}

// ---------------------------------------------------------------------------
// mma.sync bf16 GEMM with hi/lo split:
// C[m,n] = sum_k Ah*Bh + Ah*Bl + Al*Bh   (A: [M,K], B(W): [N,K], both row-major)
// CTA tile 128x128, BK=32, 8 warps, warp tile 64x32, cp.async double buffer.
// smem row stride = 40 halves (80B) -> conflict-free ldmatrix.
// ---------------------------------------------------------------------------
#define TILE_B  (128 * 80)          // one 128x32 bf16 tile (padded)
#define STAGE_B (4 * TILE_B)        // Ah, Al, Bh, Bl
#define GEMM_SMEM (2 * STAGE_B)     // 81920 bytes

__global__ __launch_bounds__(256, 1)
void gemm_mma(const __nv_bfloat16* __restrict__ Ah, const __nv_bfloat16* __restrict__ Al,
              const __nv_bfloat16* __restrict__ Bh, const __nv_bfloat16* __restrict__ Bl,
              float* __restrict__ C, int Mn, int Nn, int Kn) {
    extern __shared__ char smem[];
    const uint32_t sb = smem_u32(smem);

    const int tid = threadIdx.x;
    const int lane = tid & 31;
    const int wid = tid >> 5;
    const int wm = wid >> 2;        // 0..1 -> m offset wm*64
    const int wn = wid & 3;         // 0..3 -> n offset wn*32
    const int m0 = blockIdx.y * 128;
    const int n0 = blockIdx.x * 128;
    const int NS = Kn / 32;

    // cp.async mapping: per matrix 512 chunks of 16B (128 rows x 4 chunks)
    const int ch0 = tid;            // chunks ch0 and ch0+256
    const int r0c = ch0 >> 2, c0c = ch0 & 3;
    const int r1c = (ch0 + 256) >> 2, c1c = (ch0 + 256) & 3;

    const __nv_bfloat16* gA0h = Ah + (size_t)(m0 + r0c) * Kn + c0c * 8;
    const __nv_bfloat16* gA1h = Ah + (size_t)(m0 + r1c) * Kn + c1c * 8;
    const __nv_bfloat16* gA0l = Al + (size_t)(m0 + r0c) * Kn + c0c * 8;
    const __nv_bfloat16* gA1l = Al + (size_t)(m0 + r1c) * Kn + c1c * 8;
    const __nv_bfloat16* gB0h = Bh + (size_t)(n0 + r0c) * Kn + c0c * 8;
    const __nv_bfloat16* gB1h = Bh + (size_t)(n0 + r1c) * Kn + c1c * 8;
    const __nv_bfloat16* gB0l = Bl + (size_t)(n0 + r0c) * Kn + c0c * 8;
    const __nv_bfloat16* gB1l = Bl + (size_t)(n0 + r1c) * Kn + c1c * 8;
    const uint32_t s0 = r0c * 80 + c0c * 16;
    const uint32_t s1 = r1c * 80 + c1c * 16;

#define LOAD_STAGE(j)                                                         \
    do {                                                                      \
        const uint32_t _b = sb + ((j) & 1) * STAGE_B;                         \
        const int _kg = (j) * 32;                                             \
        CP16(_b + s0,              gA0h + _kg);                               \
        CP16(_b + s1,              gA1h + _kg);                               \
        CP16(_b + TILE_B + s0,     gA0l + _kg);                               \
        CP16(_b + TILE_B + s1,     gA1l + _kg);                               \
        CP16(_b + 2 * TILE_B + s0, gB0h + _kg);                               \
        CP16(_b + 2 * TILE_B + s1, gB1h + _kg);                               \
        CP16(_b + 3 * TILE_B + s0, gB0l + _kg);                               \
        CP16(_b + 3 * TILE_B + s1, gB1l + _kg);                               \
        CP_COMMIT();                                                          \
    } while (0)

    // ldmatrix lane offsets (bytes)
    const uint32_t aoff = (uint32_t)((wm * 64 + (lane & 15)) * 80 + (lane >> 4) * 16);
    const uint32_t boff = (uint32_t)((wn * 32 + (lane >> 4) * 8 + (lane & 7)) * 80 +
                                     ((lane >> 3) & 1) * 16);

    float acc[4][4][4];
#pragma unroll
    for (int mt = 0; mt < 4; mt++)
#pragma unroll
        for (int nt = 0; nt < 4; nt++)
#pragma unroll
            for (int q = 0; q < 4; q++) acc[mt][nt][q] = 0.f;

    LOAD_STAGE(0);

    for (int i = 0; i < NS; i++) {
        if (i + 1 < NS) { LOAD_STAGE(i + 1); CP_WAIT(1); }
        else            { CP_WAIT(0); }
        __syncthreads();

        const uint32_t base = sb + (i & 1) * STAGE_B;
        const uint32_t sAh = base + aoff;
        const uint32_t sAl = base + TILE_B + aoff;
        const uint32_t sBh = base + 2 * TILE_B + boff;
        const uint32_t sBl = base + 3 * TILE_B + boff;

#pragma unroll
        for (int k0 = 0; k0 < 2; k0++) {       // two k16 steps
            const uint32_t kb = k0 * 32;       // k16 -> 32 bytes
            uint32_t ah[4][4], al[4][4], bh[4][2], bl[4][2];
#pragma unroll
            for (int mt = 0; mt < 4; mt++) {
                LDM_X4(ah[mt][0], ah[mt][1], ah[mt][2], ah[mt][3],
                       sAh + mt * (16 * 80) + kb);
                LDM_X4(al[mt][0], al[mt][1], al[mt][2], al[mt][3],
                       sAl + mt * (16 * 80) + kb);
            }
#pragma unroll
            for (int h = 0; h < 2; h++) {
                uint32_t r0, r1, r2, r3;
                LDM_X4(r0, r1, r2, r3, sBh + h * (16 * 80) + kb);
                bh[h * 2][0] = r0; bh[h * 2][1] = r1;
                bh[h * 2 + 1][0] = r2; bh[h * 2 + 1][1] = r3;
                LDM_X4(r0, r1, r2, r3, sBl + h * (16 * 80) + kb);
                bl[h * 2][0] = r0; bl[h * 2][1] = r1;
                bl[h * 2 + 1][0] = r2; bl[h * 2 + 1][1] = r3;
            }
#pragma unroll
            for (int mt = 0; mt < 4; mt++)
#pragma unroll
                for (int nt = 0; nt < 4; nt++) {
                    MMA_BF16(acc[mt][nt], ah[mt], bh[nt]);
                    MMA_BF16(acc[mt][nt], ah[mt], bl[nt]);
                    MMA_BF16(acc[mt][nt], al[mt], bh[nt]);
                }
        }
        __syncthreads();
    }
#undef LOAD_STAGE

    // epilogue
#pragma unroll
    for (int mt = 0; mt < 4; mt++) {
        const int row = m0 + wm * 64 + mt * 16 + (lane >> 2);
#pragma unroll
        for (int nt = 0; nt < 4; nt++) {
            const int col = n0 + wn * 32 + nt * 8 + (lane & 3) * 2;
            *(float2*)&C[(size_t)row * Nn + col] =
                make_float2(acc[mt][nt][0], acc[mt][nt][1]);
            *(float2*)&C[(size_t)(row + 8) * Nn + col] =
                make_float2(acc[mt][nt][2], acc[mt][nt][3]);
        }
    }
}

// ---------------------------------------------------------------------------
// RoPE (interleaved pairs) applied in place to g_q and g_k.
// ---------------------------------------------------------------------------
__global__ void rope_kernel(float* __restrict__ q, float* __restrict__ k,
                            const float* __restrict__ cosv,
                            const float* __restrict__ sinv) {
    int idx = blockIdx.x * blockDim.x + threadIdx.x;
    if (idx >= B_ * T_ * H_ * (HD_ / 2)) return;
    int i2 = idx & 63;
    int bt = idx >> 10;
    int t = bt & (T_ - 1);
    float c = cosv[t * 64 + i2];
    float s = sinv[t * 64 + i2];
    size_t base = (size_t)idx * 2;

    float xr = q[base], xi = q[base + 1];
    q[base]     = xr * c - xi * s;
    q[base + 1] = xr * s + xi * c;

    xr = k[base]; xi = k[base + 1];
    k[base]     = xr * c - xi * s;
    k[base + 1] = xr * s + xi * c;
}

// ---------------------------------------------------------------------------
// Flash attention, fp32 (unchanged; next optimization target).
// ---------------------------------------------------------------------------
#define ATTN_SMEM_BYTES ((64 * 128 + 64 * 128 + 128 * 65) * 4)

__global__ __launch_bounds__(256, 2)
void attn_kernel(const float* __restrict__ Q, const float* __restrict__ Kg,
                 const float* __restrict__ Vg, float* __restrict__ Og) {
    extern __shared__ float sm[];
    float* Qs = sm;
    float* Vs = sm + 64 * 128;
    float* Ks = sm + 2 * 64 * 128;

    const int tid = threadIdx.x;
    const int lane = tid & 31;
    const int warp = tid >> 5;
    const int t0 = blockIdx.x * 64;
    const int h = blockIdx.y;
    const int b = blockIdx.z;
    const size_t headoff = ((size_t)b * T_ * H_ + h) * HD_;

    {
        const float* qbase = Q + headoff + (size_t)t0 * EMB_;
#pragma unroll
        for (int i = 0; i < 8; i++) {
            int f = tid + 256 * i;
            int r = f >> 5, d4 = f & 31;
            float4 v = *(const float4*)(qbase + (size_t)r * EMB_ + d4 * 4);
            *(float4*)&Qs[r * 128 + d4 * 4] = v;
        }
    }

    float m_s[8], l_s[8], acc[8][4];
#pragma unroll
    for (int r = 0; r < 8; r++) {
        m_s[r] = -CUDART_INF_F;
        l_s[r] = 0.f;
#pragma unroll
        for (int d = 0; d < 4; d++) acc[r][d] = 0.f;
    }
    const float scale = 0.08838834764831845f;

    for (int n0 = 0; n0 < T_; n0 += 64) {
        const float* kbase = Kg + headoff + (size_t)n0 * EMB_;
        const float* vbase = Vg + headoff + (size_t)n0 * EMB_;
        __syncthreads();
#pragma unroll
        for (int i = 0; i < 8; i++) {
            int f = tid + 256 * i;
            int r = f >> 5, d4 = f & 31;
            float4 kv = *(const float4*)(kbase + (size_t)r * EMB_ + d4 * 4);
            Ks[(d4 * 4 + 0) * 65 + r] = kv.x;
            Ks[(d4 * 4 + 1) * 65 + r] = kv.y;
            Ks[(d4 * 4 + 2) * 65 + r] = kv.z;
            Ks[(d4 * 4 + 3) * 65 + r] = kv.w;
            float4 vv = *(const float4*)(vbase + (size_t)r * EMB_ + d4 * 4);
            *(float4*)&Vs[r * 128 + d4 * 4] = vv;
        }
        __syncthreads();

        float s0[8], s1[8];
#pragma unroll
        for (int r = 0; r < 8; r++) { s0[r] = 0.f; s1[r] = 0.f; }
#pragma unroll 8
        for (int k4 = 0; k4 < 32; k4++) {
            float kv0[4], kv1[4];
#pragma unroll
            for (int j = 0; j < 4; j++) {
                kv0[j] = Ks[(k4 * 4 + j) * 65 + lane];
                kv1[j] = Ks[(k4 * 4 + j) * 65 + 32 + lane];
            }
#pragma unroll
            for (int r = 0; r < 8; r++) {
                float4 q4 = *(const float4*)&Qs[(warp * 8 + r) * 128 + k4 * 4];
                s0[r] += q4.x * kv0[0] + q4.y * kv0[1] + q4.z * kv0[2] + q4.w * kv0[3];
                s1[r] += q4.x * kv1[0] + q4.y * kv1[1] + q4.z * kv1[2] + q4.w * kv1[3];
            }
        }

        float ps0[8], ps1[8];
#pragma unroll
        for (int r = 0; r < 8; r++) {
            float a0 = s0[r] * scale;
            float a1 = s1[r] * scale;
            float mt = fmaxf(a0, a1);
#pragma unroll
            for (int off = 16; off; off >>= 1)
                mt = fmaxf(mt, __shfl_xor_sync(0xffffffffu, mt, off));
            float mnew = fmaxf(m_s[r], mt);
            float alpha = __expf(m_s[r] - mnew);
            float p0 = __expf(a0 - mnew);
            float p1 = __expf(a1 - mnew);
            float rs = p0 + p1;
#pragma unroll
            for (int off = 16; off; off >>= 1)
                rs += __shfl_xor_sync(0xffffffffu, rs, off);
            l_s[r] = l_s[r] * alpha + rs;
            m_s[r] = mnew;
#pragma unroll
            for (int d = 0; d < 4; d++) acc[r][d] *= alpha;
            ps0[r] = p0;
            ps1[r] = p1;
        }

#pragma unroll
        for (int chunk = 0; chunk < 2; chunk++) {
#pragma unroll 8
            for (int ls = 0; ls < 32; ls++) {
                int c = chunk * 32 + ls;
                float v0 = Vs[c * 128 + lane];
                float v1 = Vs[c * 128 + 32 + lane];
                float v2 = Vs[c * 128 + 64 + lane];
                float v3 = Vs[c * 128 + 96 + lane];
#pragma unroll
                for (int r = 0; r < 8; r++) {
                    float pb = __shfl_sync(0xffffffffu,
                                           chunk ? ps1[r] : ps0[r], ls);
                    acc[r][0] += pb * v0;
                    acc[r][1] += pb * v1;
                    acc[r][2] += pb * v2;
                    acc[r][3] += pb * v3;
                }
            }
        }
    }

#pragma unroll
    for (int r = 0; r < 8; r++) {
        int row = warp * 8 + r;
        float inv = 1.f / l_s[r];
        float* ob = Og + headoff + (size_t)(t0 + row) * EMB_;
        ob[lane]      = acc[r][0] * inv;
        ob[32 + lane] = acc[r][1] * inv;
        ob[64 + lane] = acc[r][2] * inv;
        ob[96 + lane] = acc[r][3] * inv;
    }
}

// ---------------------------------------------------------------------------
extern "C" void kernel_launch(void* const* d_in, const int* in_sizes, int n_in,
                              void* d_out, int out_size) {
    const float* x    = (const float*)d_in[0];
    const float* wq   = (const float*)d_in[1];
    const float* wk   = (const float*)d_in[2];
    const float* wv   = (const float*)d_in[3];
    const float* wo   = (const float*)d_in[4];
    const float* fcos = (const float*)d_in[7];
    const float* fsin = (const float*)d_in[8];
    float* out = (float*)d_out;

    float *gq, *gk, *gv, *gattn;
    __nv_bfloat16 *gxh, *gxl, *gwh, *gwl, *gah, *gal;
    cudaGetSymbolAddress((void**)&gq, g_q);
    cudaGetSymbolAddress((void**)&gk, g_k);
    cudaGetSymbolAddress((void**)&gv, g_v);
    cudaGetSymbolAddress((void**)&gattn, g_attn);
    cudaGetSymbolAddress((void**)&gxh, g_xh);
    cudaGetSymbolAddress((void**)&gxl, g_xl);
    cudaGetSymbolAddress((void**)&gwh, g_wh);
    cudaGetSymbolAddress((void**)&gwl, g_wl);
    cudaGetSymbolAddress((void**)&gah, g_ah);
    cudaGetSymbolAddress((void**)&gal, g_al);

    cudaFuncSetAttribute(attn_kernel,
                         cudaFuncAttributeMaxDynamicSharedMemorySize,
                         ATTN_SMEM_BYTES);
    cudaFuncSetAttribute(gemm_mma,
                         cudaFuncAttributeMaxDynamicSharedMemorySize,
                         GEMM_SMEM);

    const size_t WSZ = (size_t)EMB_ * EMB_;
    const int n4x = (M_ * EMB_) / 4;
    const int n4w = (EMB_ * EMB_) / 4;

    cvt_hilo<<<(n4x + 255) / 256, 256>>>(x, gxh, gxl, n4x);
    cvt_hilo<<<(n4w + 255) / 256, 256>>>(wq, gwh + 0 * WSZ, gwl + 0 * WSZ, n4w);
    cvt_hilo<<<(n4w + 255) / 256, 256>>>(wk, gwh + 1 * WSZ, gwl + 1 * WSZ, n4w);
    cvt_hilo<<<(n4w + 255) / 256, 256>>>(wv, gwh + 2 * WSZ, gwl + 2 * WSZ, n4w);
    cvt_hilo<<<(n4w + 255) / 256, 256>>>(wo, gwh + 3 * WSZ, gwl + 3 * WSZ, n4w);

    dim3 ggrid(EMB_ / 128, M_ / 128);
    gemm_mma<<<ggrid, 256, GEMM_SMEM>>>(gxh, gxl, gwh + 0 * WSZ, gwl + 0 * WSZ,
                                        gq, M_, EMB_, EMB_);
    gemm_mma<<<ggrid, 256, GEMM_SMEM>>>(gxh, gxl, gwh + 1 * WSZ, gwl + 1 * WSZ,
                                        gk, M_, EMB_, EMB_);
    gemm_mma<<<ggrid, 256, GEMM_SMEM>>>(gxh, gxl, gwh + 2 * WSZ, gwl + 2 * WSZ,
                                        gv, M_, EMB_, EMB_);

    int nrope = B_ * T_ * H_ * (HD_ / 2);
    rope_kernel<<<(nrope + 255) / 256, 256>>>(gq, gk, fcos, fsin);

    dim3 agrid(T_ / 64, H_, B_);
    attn_kernel<<<agrid, 256, ATTN_SMEM_BYTES>>>(gq, gk, gv, gattn);

    cvt_hilo<<<(n4x + 255) / 256, 256>>>(gattn, gah, gal, n4x);
    gemm_mma<<<ggrid, 256, GEMM_SMEM>>>(gah, gal, gwh + 3 * WSZ, gwl + 3 * WSZ,
                                        out, M_, EMB_, EMB_);
}

// round 7
// speedup vs baseline: 2.7545x; 1.7213x over previous
#include <cuda_runtime.h>
#include <cuda_bf16.h>
#include <math_constants.h>
#include <cstdint>

#define B_   2
#define T_   2048
#define EMB_ 2048
#define H_   16
#define HD_  128
#define M_   (B_ * T_)   // 4096

// ---------------------------------------------------------------------------
// Scratch (__device__ globals; no allocation allowed)
// ---------------------------------------------------------------------------
__device__ float g_q[(size_t)M_ * EMB_];
__device__ float g_k[(size_t)M_ * EMB_];
__device__ float g_v[(size_t)M_ * EMB_];
__device__ __nv_bfloat16 g_xh[(size_t)M_ * EMB_];
__device__ __nv_bfloat16 g_xl[(size_t)M_ * EMB_];
__device__ __nv_bfloat16 g_wh[4][(size_t)EMB_ * EMB_];
__device__ __nv_bfloat16 g_wl[4][(size_t)EMB_ * EMB_];
__device__ __nv_bfloat16 g_ah[(size_t)M_ * EMB_];
__device__ __nv_bfloat16 g_al[(size_t)M_ * EMB_];
__device__ __nv_bfloat16 g_qh[(size_t)M_ * EMB_];
__device__ __nv_bfloat16 g_ql[(size_t)M_ * EMB_];
__device__ __nv_bfloat16 g_kh[(size_t)M_ * EMB_];
__device__ __nv_bfloat16 g_kl[(size_t)M_ * EMB_];
__device__ __nv_bfloat16 g_vh[(size_t)M_ * EMB_];
__device__ __nv_bfloat16 g_vl[(size_t)M_ * EMB_];

// ---------------------------------------------------------------------------
// helpers
// ---------------------------------------------------------------------------
__device__ __forceinline__ uint32_t smem_u32(const void* p) {
    uint32_t a;
    asm("{ .reg .u64 t; cvta.to.shared.u64 t, %1; cvt.u32.u64 %0, t; }"
        : "=r"(a) : "l"(p));
    return a;
}
#define CP16(dst, src) \
    asm volatile("cp.async.cg.shared.global [%0], [%1], 16;" \
                 :: "r"(dst), "l"(src))
#define CP_COMMIT() asm volatile("cp.async.commit_group;" ::: "memory")
#define CP_WAIT(n)  asm volatile("cp.async.wait_group %0;" :: "n"(n) : "memory")

#define LDM_X4(r0, r1, r2, r3, addr)                                          \
    asm volatile("ldmatrix.sync.aligned.m8n8.x4.shared.b16 {%0,%1,%2,%3}, [%4];" \
                 : "=r"(r0), "=r"(r1), "=r"(r2), "=r"(r3) : "r"(addr))

#define LDM_X4T(r0, r1, r2, r3, addr)                                         \
    asm volatile("ldmatrix.sync.aligned.m8n8.x4.trans.shared.b16 {%0,%1,%2,%3}, [%4];" \
                 : "=r"(r0), "=r"(r1), "=r"(r2), "=r"(r3) : "r"(addr))

#define MMA_BF16(d, a, b)                                                     \
    asm volatile("mma.sync.aligned.m16n8k16.row.col.f32.bf16.bf16.f32 "       \
                 "{%0,%1,%2,%3}, {%4,%5,%6,%7}, {%8,%9}, {%0,%1,%2,%3};"      \
                 : "+f"((d)[0]), "+f"((d)[1]), "+f"((d)[2]), "+f"((d)[3])     \
                 : "r"((a)[0]), "r"((a)[1]), "r"((a)[2]), "r"((a)[3]),        \
                   "r"((b)[0]), "r"((b)[1]))

__device__ __forceinline__ uint32_t pack_bf16(float lo, float hi) {
    uint32_t r;
    asm("cvt.rn.bf16x2.f32 %0, %1, %2;" : "=r"(r) : "f"(hi), "f"(lo));
    return r;
}
__device__ __forceinline__ float2 unpack_bf16(uint32_t v) {
    __nv_bfloat162 h = *reinterpret_cast<__nv_bfloat162*>(&v);
    return __bfloat1622float2(h);
}

// ---------------------------------------------------------------------------
// fp32 -> bf16 hi/lo split
// ---------------------------------------------------------------------------
__global__ void cvt_hilo(const float* __restrict__ src,
                         __nv_bfloat16* __restrict__ hi,
                         __nv_bfloat16* __restrict__ lo, int n4) {
    int i = blockIdx.x * blockDim.x + threadIdx.x;
    if (i >= n4) return;
    float4 v = ((const float4*)src)[i];
    uint32_t h01 = pack_bf16(v.x, v.y);
    uint32_t h23 = pack_bf16(v.z, v.w);
    float2 b01 = unpack_bf16(h01);
    float2 b23 = unpack_bf16(h23);
    uint32_t l01 = pack_bf16(v.x - b01.x, v.y - b01.y);
    uint32_t l23 = pack_bf16(v.z - b23.x, v.w - b23.y);
    ((uint2*)hi)[i] = make_uint2(h01, h23);
    ((uint2*)lo)[i] = make_uint2(l01, l23);
}

// ---------------------------------------------------------------------------
// RoPE + hi/lo split (q scaled by 1/sqrt(HD))
// ---------------------------------------------------------------------------
__global__ void rope_cvt(const float* __restrict__ q, const float* __restrict__ k,
                         const float* __restrict__ cosv, const float* __restrict__ sinv,
                         __nv_bfloat16* __restrict__ qh, __nv_bfloat16* __restrict__ ql,
                         __nv_bfloat16* __restrict__ kh, __nv_bfloat16* __restrict__ kl) {
    int idx = blockIdx.x * blockDim.x + threadIdx.x;
    if (idx >= B_ * T_ * H_ * (HD_ / 2)) return;
    int i2 = idx & 63;
    int t = (idx >> 10) & (T_ - 1);
    float c = cosv[t * 64 + i2];
    float s = sinv[t * 64 + i2];
    size_t base = (size_t)idx * 2;
    const float sc = 0.08838834764831845f;

    float xr = q[base], xi = q[base + 1];
    float qr = (xr * c - xi * s) * sc;
    float qi = (xr * s + xi * c) * sc;
    uint32_t qhp = pack_bf16(qr, qi);
    float2 qb = unpack_bf16(qhp);
    uint32_t qlp = pack_bf16(qr - qb.x, qi - qb.y);
    *(uint32_t*)(qh + base) = qhp;
    *(uint32_t*)(ql + base) = qlp;

    xr = k[base]; xi = k[base + 1];
    float kr = xr * c - xi * s;
    float ki = xr * s + xi * c;
    uint32_t khp = pack_bf16(kr, ki);
    float2 kb = unpack_bf16(khp);
    uint32_t klp = pack_bf16(kr - kb.x, ki - kb.y);
    *(uint32_t*)(kh + base) = khp;
    *(uint32_t*)(kl + base) = klp;
}

// ---------------------------------------------------------------------------
// mma.sync bf16 GEMM with hi/lo split (unchanged from R6)
// ---------------------------------------------------------------------------
#define TILE_B  (128 * 80)
#define STAGE_B (4 * TILE_B)
#define GEMM_SMEM (2 * STAGE_B)

__global__ __launch_bounds__(256, 1)
void gemm_mma(const __nv_bfloat16* __restrict__ Ah, const __nv_bfloat16* __restrict__ Al,
              const __nv_bfloat16* __restrict__ Bh, const __nv_bfloat16* __restrict__ Bl,
              float* __restrict__ C, int Mn, int Nn, int Kn) {
    extern __shared__ char smem[];
    const uint32_t sb = smem_u32(smem);

    const int tid = threadIdx.x;
    const int lane = tid & 31;
    const int wid = tid >> 5;
    const int wm = wid >> 2;
    const int wn = wid & 3;
    const int m0 = blockIdx.y * 128;
    const int n0 = blockIdx.x * 128;
    const int NS = Kn / 32;

    const int ch0 = tid;
    const int r0c = ch0 >> 2, c0c = ch0 & 3;
    const int r1c = (ch0 + 256) >> 2, c1c = (ch0 + 256) & 3;

    const __nv_bfloat16* gA0h = Ah + (size_t)(m0 + r0c) * Kn + c0c * 8;
    const __nv_bfloat16* gA1h = Ah + (size_t)(m0 + r1c) * Kn + c1c * 8;
    const __nv_bfloat16* gA0l = Al + (size_t)(m0 + r0c) * Kn + c0c * 8;
    const __nv_bfloat16* gA1l = Al + (size_t)(m0 + r1c) * Kn + c1c * 8;
    const __nv_bfloat16* gB0h = Bh + (size_t)(n0 + r0c) * Kn + c0c * 8;
    const __nv_bfloat16* gB1h = Bh + (size_t)(n0 + r1c) * Kn + c1c * 8;
    const __nv_bfloat16* gB0l = Bl + (size_t)(n0 + r0c) * Kn + c0c * 8;
    const __nv_bfloat16* gB1l = Bl + (size_t)(n0 + r1c) * Kn + c1c * 8;
    const uint32_t s0 = r0c * 80 + c0c * 16;
    const uint32_t s1 = r1c * 80 + c1c * 16;

#define LOAD_STAGE(j)                                                         \
    do {                                                                      \
        const uint32_t _b = sb + ((j) & 1) * STAGE_B;                         \
        const int _kg = (j) * 32;                                             \
        CP16(_b + s0,              gA0h + _kg);                               \
        CP16(_b + s1,              gA1h + _kg);                               \
        CP16(_b + TILE_B + s0,     gA0l + _kg);                               \
        CP16(_b + TILE_B + s1,     gA1l + _kg);                               \
        CP16(_b + 2 * TILE_B + s0, gB0h + _kg);                               \
        CP16(_b + 2 * TILE_B + s1, gB1h + _kg);                               \
        CP16(_b + 3 * TILE_B + s0, gB0l + _kg);                               \
        CP16(_b + 3 * TILE_B + s1, gB1l + _kg);                               \
        CP_COMMIT();                                                          \
    } while (0)

    const uint32_t aoff = (uint32_t)((wm * 64 + (lane & 15)) * 80 + (lane >> 4) * 16);
    const uint32_t boff = (uint32_t)((wn * 32 + (lane >> 4) * 8 + (lane & 7)) * 80 +
                                     ((lane >> 3) & 1) * 16);

    float acc[4][4][4];
#pragma unroll
    for (int mt = 0; mt < 4; mt++)
#pragma unroll
        for (int nt = 0; nt < 4; nt++)
#pragma unroll
            for (int q = 0; q < 4; q++) acc[mt][nt][q] = 0.f;

    LOAD_STAGE(0);

    for (int i = 0; i < NS; i++) {
        if (i + 1 < NS) { LOAD_STAGE(i + 1); CP_WAIT(1); }
        else            { CP_WAIT(0); }
        __syncthreads();

        const uint32_t base = sb + (i & 1) * STAGE_B;
        const uint32_t sAh = base + aoff;
        const uint32_t sAl = base + TILE_B + aoff;
        const uint32_t sBh = base + 2 * TILE_B + boff;
        const uint32_t sBl = base + 3 * TILE_B + boff;

#pragma unroll
        for (int k0 = 0; k0 < 2; k0++) {
            const uint32_t kb = k0 * 32;
            uint32_t ah[4][4], al[4][4], bh[4][2], bl[4][2];
#pragma unroll
            for (int mt = 0; mt < 4; mt++) {
                LDM_X4(ah[mt][0], ah[mt][1], ah[mt][2], ah[mt][3],
                       sAh + mt * (16 * 80) + kb);
                LDM_X4(al[mt][0], al[mt][1], al[mt][2], al[mt][3],
                       sAl + mt * (16 * 80) + kb);
            }
#pragma unroll
            for (int h = 0; h < 2; h++) {
                uint32_t r0, r1, r2, r3;
                LDM_X4(r0, r1, r2, r3, sBh + h * (16 * 80) + kb);
                bh[h * 2][0] = r0; bh[h * 2][1] = r1;
                bh[h * 2 + 1][0] = r2; bh[h * 2 + 1][1] = r3;
                LDM_X4(r0, r1, r2, r3, sBl + h * (16 * 80) + kb);
                bl[h * 2][0] = r0; bl[h * 2][1] = r1;
                bl[h * 2 + 1][0] = r2; bl[h * 2 + 1][1] = r3;
            }
#pragma unroll
            for (int mt = 0; mt < 4; mt++)
#pragma unroll
                for (int nt = 0; nt < 4; nt++) {
                    MMA_BF16(acc[mt][nt], ah[mt], bh[nt]);
                    MMA_BF16(acc[mt][nt], ah[mt], bl[nt]);
                    MMA_BF16(acc[mt][nt], al[mt], bh[nt]);
                }
        }
        __syncthreads();
    }
#undef LOAD_STAGE

#pragma unroll
    for (int mt = 0; mt < 4; mt++) {
        const int row = m0 + wm * 64 + mt * 16 + (lane >> 2);
#pragma unroll
        for (int nt = 0; nt < 4; nt++) {
            const int col = n0 + wn * 32 + nt * 8 + (lane & 3) * 2;
            *(float2*)&C[(size_t)row * Nn + col] =
                make_float2(acc[mt][nt][0], acc[mt][nt][1]);
            *(float2*)&C[(size_t)(row + 8) * Nn + col] =
                make_float2(acc[mt][nt][2], acc[mt][nt][3]);
        }
    }
}

// ---------------------------------------------------------------------------
// Tensor-core flash attention, bf16 hi/lo split throughout.
// CTA: 128 q-rows x full head. 8 warps, warp = 16 q-rows.
// Key tiles of 64; K/V double-buffered cp.async; Q resident in smem.
// Q/K/V smem row stride = 136 halves (272B) -> conflict-free ldmatrix.
// Output written directly as bf16 hi/lo split (feeds W_o GEMM).
// smem: Qh(34816) Ql(34816) + 2 stages x {Kh,Kl,Vh,Vl}(17408 each) = 208896 B.
// ---------------------------------------------------------------------------
#define AT_QB    34816
#define AT_KVT   17408
#define AT_STAGEB (4 * AT_KVT)
#define ATTN_SMEM (2 * AT_QB + 2 * AT_STAGEB)

__global__ __launch_bounds__(256, 1)
void attn_mma(const __nv_bfloat16* __restrict__ qh, const __nv_bfloat16* __restrict__ ql,
              const __nv_bfloat16* __restrict__ kh, const __nv_bfloat16* __restrict__ kl,
              const __nv_bfloat16* __restrict__ vh, const __nv_bfloat16* __restrict__ vl,
              __nv_bfloat16* __restrict__ oh, __nv_bfloat16* __restrict__ ol) {
    extern __shared__ char smem[];
    const uint32_t sb = smem_u32(smem);
    const int tid = threadIdx.x;
    const int lane = tid & 31;
    const int wid = tid >> 5;
    const int qt0 = blockIdx.x * 128;
    const int h = blockIdx.y;
    const int b = blockIdx.z;
    const int bT = b * T_;
    const size_t headcol = (size_t)h * HD_;

    // ---- load Q (128 rows x 128 hd, hi+lo)
#pragma unroll
    for (int it = 0; it < 8; it++) {
        int x = tid + it * 256;
        int row = x >> 4, c = x & 15;
        size_t g = (size_t)(bT + qt0 + row) * EMB_ + headcol + c * 8;
        CP16(sb + row * 272 + c * 16, qh + g);
        CP16(sb + AT_QB + row * 272 + c * 16, ql + g);
    }

#define AT_STAGE(j)                                                            \
    do {                                                                       \
        const uint32_t bs_ = sb + 2 * AT_QB + ((j) & 1) * AT_STAGEB;           \
        const int kt_ = (j) * 64;                                              \
        _Pragma("unroll")                                                      \
        for (int it = 0; it < 16; it++) {                                      \
            int x = tid + it * 256;                                            \
            int tsel = x >> 10;                                                \
            int w = x & 1023;                                                  \
            int row = w >> 4, c = w & 15;                                      \
            size_t g = (size_t)(bT + kt_ + row) * EMB_ + headcol + c * 8;      \
            const __nv_bfloat16* p = (tsel == 0) ? kh : (tsel == 1) ? kl       \
                                   : (tsel == 2) ? vh : vl;                    \
            CP16(bs_ + tsel * AT_KVT + row * 272 + c * 16, p + g);             \
        }                                                                      \
        CP_COMMIT();                                                           \
    } while (0)

    AT_STAGE(0);

    // lane-invariant smem offsets
    const uint32_t aoff = (uint32_t)((wid * 16 + (lane & 15)) * 272 + (lane >> 4) * 16);
    const uint32_t koff = (uint32_t)(((lane >> 4) * 8 + (lane & 7)) * 272 +
                                     ((lane >> 3) & 1) * 16);
    const uint32_t voff = (uint32_t)((((lane >> 3) & 1) * 8 + (lane & 7)) * 272 +
                                     (lane >> 4) * 16);

    float acc_o[16][4];
#pragma unroll
    for (int nt = 0; nt < 16; nt++)
#pragma unroll
        for (int q = 0; q < 4; q++) acc_o[nt][q] = 0.f;
    float m0 = -CUDART_INF_F, m1 = -CUDART_INF_F;
    float l0 = 0.f, l1 = 0.f;

    for (int it = 0; it < T_ / 64; it++) {
        if (it + 1 < T_ / 64) { AT_STAGE(it + 1); CP_WAIT(1); }
        else                  { CP_WAIT(0); }
        __syncthreads();

        const uint32_t bs = sb + 2 * AT_QB + (it & 1) * AT_STAGEB;

        // ---- S = Q K^T (3-term split) -> accs[8 nt][4]
        float accs[8][4];
#pragma unroll
        for (int nt = 0; nt < 8; nt++)
#pragma unroll
            for (int q = 0; q < 4; q++) accs[nt][q] = 0.f;

#pragma unroll
        for (int ks = 0; ks < 8; ks++) {
            uint32_t aH[4], aL[4];
            LDM_X4(aH[0], aH[1], aH[2], aH[3], sb + aoff + ks * 32);
            LDM_X4(aL[0], aL[1], aL[2], aL[3], sb + AT_QB + aoff + ks * 32);
#pragma unroll
            for (int jn = 0; jn < 4; jn++) {
                uint32_t r0, r1, r2, r3;
                uint32_t bH[2][2], bL[2][2];
                LDM_X4(r0, r1, r2, r3, bs + jn * (16 * 272) + koff + ks * 32);
                bH[0][0] = r0; bH[0][1] = r1; bH[1][0] = r2; bH[1][1] = r3;
                LDM_X4(r0, r1, r2, r3, bs + AT_KVT + jn * (16 * 272) + koff + ks * 32);
                bL[0][0] = r0; bL[0][1] = r1; bL[1][0] = r2; bL[1][1] = r3;
#pragma unroll
                for (int q = 0; q < 2; q++) {
                    MMA_BF16(accs[jn * 2 + q], aH, bH[q]);
                    MMA_BF16(accs[jn * 2 + q], aH, bL[q]);
                    MMA_BF16(accs[jn * 2 + q], aL, bH[q]);
                }
            }
        }

        // ---- online softmax (rows r = lane>>2 and r+8)
        float rm0 = accs[0][0], rm1 = accs[0][2];
#pragma unroll
        for (int nt = 0; nt < 8; nt++) {
            rm0 = fmaxf(rm0, fmaxf(accs[nt][0], accs[nt][1]));
            rm1 = fmaxf(rm1, fmaxf(accs[nt][2], accs[nt][3]));
        }
        rm0 = fmaxf(rm0, __shfl_xor_sync(0xffffffffu, rm0, 1));
        rm0 = fmaxf(rm0, __shfl_xor_sync(0xffffffffu, rm0, 2));
        rm1 = fmaxf(rm1, __shfl_xor_sync(0xffffffffu, rm1, 1));
        rm1 = fmaxf(rm1, __shfl_xor_sync(0xffffffffu, rm1, 2));

        float mn0 = fmaxf(m0, rm0);
        float mn1 = fmaxf(m1, rm1);
        float al0 = __expf(m0 - mn0);
        float al1 = __expf(m1 - mn1);
        m0 = mn0; m1 = mn1;

        float rs0 = 0.f, rs1 = 0.f;
#pragma unroll
        for (int nt = 0; nt < 8; nt++) {
            accs[nt][0] = __expf(accs[nt][0] - m0);
            accs[nt][1] = __expf(accs[nt][1] - m0);
            accs[nt][2] = __expf(accs[nt][2] - m1);
            accs[nt][3] = __expf(accs[nt][3] - m1);
            rs0 += accs[nt][0] + accs[nt][1];
            rs1 += accs[nt][2] + accs[nt][3];
        }
        rs0 += __shfl_xor_sync(0xffffffffu, rs0, 1);
        rs0 += __shfl_xor_sync(0xffffffffu, rs0, 2);
        rs1 += __shfl_xor_sync(0xffffffffu, rs1, 1);
        rs1 += __shfl_xor_sync(0xffffffffu, rs1, 2);
        l0 = l0 * al0 + rs0;
        l1 = l1 * al1 + rs1;

#pragma unroll
        for (int nt = 0; nt < 16; nt++) {
            acc_o[nt][0] *= al0;
            acc_o[nt][1] *= al0;
            acc_o[nt][2] *= al1;
            acc_o[nt][3] *= al1;
        }

        // ---- pack P fragments (hi/lo): aP[ks2] covers keys ks2*16..+15
        uint32_t aPh[4][4], aPl[4][4];
#pragma unroll
        for (int ks2 = 0; ks2 < 4; ks2++) {
#pragma unroll
            for (int half = 0; half < 2; half++) {
                int nt = ks2 * 2 + half;
                uint32_t h01 = pack_bf16(accs[nt][0], accs[nt][1]);
                uint32_t h23 = pack_bf16(accs[nt][2], accs[nt][3]);
                float2 b01 = unpack_bf16(h01);
                float2 b23 = unpack_bf16(h23);
                uint32_t l01 = pack_bf16(accs[nt][0] - b01.x, accs[nt][1] - b01.y);
                uint32_t l23 = pack_bf16(accs[nt][2] - b23.x, accs[nt][3] - b23.y);
                aPh[ks2][half * 2]     = h01;
                aPh[ks2][half * 2 + 1] = h23;
                aPl[ks2][half * 2]     = l01;
                aPl[ks2][half * 2 + 1] = l23;
            }
        }

        // ---- O += P V (3-term split), V via ldmatrix.trans
        const uint32_t vbh = bs + 2 * AT_KVT + voff;
        const uint32_t vbl = bs + 3 * AT_KVT + voff;
#pragma unroll
        for (int ks2 = 0; ks2 < 4; ks2++) {
#pragma unroll
            for (int j = 0; j < 8; j++) {
                uint32_t r0, r1, r2, r3;
                uint32_t bv[2][2], bw[2][2];
                LDM_X4T(r0, r1, r2, r3, vbh + ks2 * (16 * 272) + j * 32);
                bv[0][0] = r0; bv[0][1] = r1; bv[1][0] = r2; bv[1][1] = r3;
                LDM_X4T(r0, r1, r2, r3, vbl + ks2 * (16 * 272) + j * 32);
                bw[0][0] = r0; bw[0][1] = r1; bw[1][0] = r2; bw[1][1] = r3;
#pragma unroll
                for (int q = 0; q < 2; q++) {
                    MMA_BF16(acc_o[j * 2 + q], aPh[ks2], bv[q]);
                    MMA_BF16(acc_o[j * 2 + q], aPh[ks2], bw[q]);
                    MMA_BF16(acc_o[j * 2 + q], aPl[ks2], bv[q]);
                }
            }
        }
        __syncthreads();
    }
#undef AT_STAGE

    // ---- epilogue: normalize, split to bf16 hi/lo, store
    const float inv0 = 1.f / l0;
    const float inv1 = 1.f / l1;
    const size_t gr0 = (size_t)(bT + qt0 + wid * 16 + (lane >> 2)) * EMB_ +
                       headcol + (lane & 3) * 2;
    const size_t gr1 = gr0 + 8 * EMB_;
#pragma unroll
    for (int nt = 0; nt < 16; nt++) {
        float f0 = acc_o[nt][0] * inv0, f1 = acc_o[nt][1] * inv0;
        float f2 = acc_o[nt][2] * inv1, f3 = acc_o[nt][3] * inv1;
        uint32_t h01 = pack_bf16(f0, f1);
        uint32_t h23 = pack_bf16(f2, f3);
        float2 b01 = unpack_bf16(h01);
        float2 b23 = unpack_bf16(h23);
        uint32_t l01 = pack_bf16(f0 - b01.x, f1 - b01.y);
        uint32_t l23 = pack_bf16(f2 - b23.x, f3 - b23.y);
        *(uint32_t*)(oh + gr0 + nt * 8) = h01;
        *(uint32_t*)(ol + gr0 + nt * 8) = l01;
        *(uint32_t*)(oh + gr1 + nt * 8) = h23;
        *(uint32_t*)(ol + gr1 + nt * 8) = l23;
    }
}

// ---------------------------------------------------------------------------
extern "C" void kernel_launch(void* const* d_in, const int* in_sizes, int n_in,
                              void* d_out, int out_size) {
    const float* x    = (const float*)d_in[0];
    const float* wq   = (const float*)d_in[1];
    const float* wk   = (const float*)d_in[2];
    const float* wv   = (const float*)d_in[3];
    const float* wo   = (const float*)d_in[4];
    const float* fcos = (const float*)d_in[7];
    const float* fsin = (const float*)d_in[8];
    float* out = (float*)d_out;

    float *gq, *gk, *gv;
    __nv_bfloat16 *gxh, *gxl, *gwh, *gwl, *gah, *gal;
    __nv_bfloat16 *gqh, *gql, *gkh, *gkl, *gvh, *gvl;
    cudaGetSymbolAddress((void**)&gq, g_q);
    cudaGetSymbolAddress((void**)&gk, g_k);
    cudaGetSymbolAddress((void**)&gv, g_v);
    cudaGetSymbolAddress((void**)&gxh, g_xh);
    cudaGetSymbolAddress((void**)&gxl, g_xl);
    cudaGetSymbolAddress((void**)&gwh, g_wh);
    cudaGetSymbolAddress((void**)&gwl, g_wl);
    cudaGetSymbolAddress((void**)&gah, g_ah);
    cudaGetSymbolAddress((void**)&gal, g_al);
    cudaGetSymbolAddress((void**)&gqh, g_qh);
    cudaGetSymbolAddress((void**)&gql, g_ql);
    cudaGetSymbolAddress((void**)&gkh, g_kh);
    cudaGetSymbolAddress((void**)&gkl, g_kl);
    cudaGetSymbolAddress((void**)&gvh, g_vh);
    cudaGetSymbolAddress((void**)&gvl, g_vl);

    cudaFuncSetAttribute(gemm_mma,
                         cudaFuncAttributeMaxDynamicSharedMemorySize, GEMM_SMEM);
    cudaFuncSetAttribute(attn_mma,
                         cudaFuncAttributeMaxDynamicSharedMemorySize, ATTN_SMEM);

    const size_t WSZ = (size_t)EMB_ * EMB_;
    const int n4x = (M_ * EMB_) / 4;
    const int n4w = (EMB_ * EMB_) / 4;

    cvt_hilo<<<(n4x + 255) / 256, 256>>>(x, gxh, gxl, n4x);
    cvt_hilo<<<(n4w + 255) / 256, 256>>>(wq, gwh + 0 * WSZ, gwl + 0 * WSZ, n4w);
    cvt_hilo<<<(n4w + 255) / 256, 256>>>(wk, gwh + 1 * WSZ, gwl + 1 * WSZ, n4w);
    cvt_hilo<<<(n4w + 255) / 256, 256>>>(wv, gwh + 2 * WSZ, gwl + 2 * WSZ, n4w);
    cvt_hilo<<<(n4w + 255) / 256, 256>>>(wo, gwh + 3 * WSZ, gwl + 3 * WSZ, n4w);

    dim3 ggrid(EMB_ / 128, M_ / 128);
    gemm_mma<<<ggrid, 256, GEMM_SMEM>>>(gxh, gxl, gwh + 0 * WSZ, gwl + 0 * WSZ,
                                        gq, M_, EMB_, EMB_);
    gemm_mma<<<ggrid, 256, GEMM_SMEM>>>(gxh, gxl, gwh + 1 * WSZ, gwl + 1 * WSZ,
                                        gk, M_, EMB_, EMB_);
    gemm_mma<<<ggrid, 256, GEMM_SMEM>>>(gxh, gxl, gwh + 2 * WSZ, gwl + 2 * WSZ,
                                        gv, M_, EMB_, EMB_);

    int nrope = B_ * T_ * H_ * (HD_ / 2);
    rope_cvt<<<(nrope + 255) / 256, 256>>>(gq, gk, fcos, fsin,
                                           gqh, gql, gkh, gkl);
    cvt_hilo<<<(n4x + 255) / 256, 256>>>(gv, gvh, gvl, n4x);

    dim3 agrid(T_ / 128, H_, B_);
    attn_mma<<<agrid, 256, ATTN_SMEM>>>(gqh, gql, gkh, gkl, gvh, gvl, gah, gal);

    gemm_mma<<<ggrid, 256, GEMM_SMEM>>>(gah, gal, gwh + 3 * WSZ, gwl + 3 * WSZ,
                                        out, M_, EMB_, EMB_);
}

// round 11
// speedup vs baseline: 2.9538x; 1.0723x over previous
#include <cuda_runtime.h>
#include <cuda_bf16.h>
#include <math_constants.h>
#include <cstdint>

#define B_   2
#define T_   2048
#define EMB_ 2048
#define H_   16
#define HD_  128
#define M_   (B_ * T_)   // 4096

// ---------------------------------------------------------------------------
// Scratch (__device__ globals; no allocation allowed)
// ---------------------------------------------------------------------------
__device__ __nv_bfloat16 g_xh[(size_t)M_ * EMB_];
__device__ __nv_bfloat16 g_xl[(size_t)M_ * EMB_];
__device__ __nv_bfloat16 g_wh[4][(size_t)EMB_ * EMB_];
__device__ __nv_bfloat16 g_wl[4][(size_t)EMB_ * EMB_];
__device__ __nv_bfloat16 g_ah[(size_t)M_ * EMB_];
__device__ __nv_bfloat16 g_al[(size_t)M_ * EMB_];
__device__ __nv_bfloat16 g_qh[(size_t)M_ * EMB_];
__device__ __nv_bfloat16 g_ql[(size_t)M_ * EMB_];
__device__ __nv_bfloat16 g_kh[(size_t)M_ * EMB_];
__device__ __nv_bfloat16 g_kl[(size_t)M_ * EMB_];
__device__ __nv_bfloat16 g_vh[(size_t)M_ * EMB_];
__device__ __nv_bfloat16 g_vl[(size_t)M_ * EMB_];

// ---------------------------------------------------------------------------
// helpers
// ---------------------------------------------------------------------------
__device__ __forceinline__ uint32_t smem_u32(const void* p) {
    uint32_t a;
    asm("{ .reg .u64 t; cvta.to.shared.u64 t, %1; cvt.u32.u64 %0, t; }"
        : "=r"(a) : "l"(p));
    return a;
}
#define CP16(dst, src) \
    asm volatile("cp.async.cg.shared.global [%0], [%1], 16;" \
                 :: "r"(dst), "l"(src))
#define CP_COMMIT() asm volatile("cp.async.commit_group;" ::: "memory")
#define CP_WAIT(n)  asm volatile("cp.async.wait_group %0;" :: "n"(n) : "memory")

#define LDM_X4(r0, r1, r2, r3, addr)                                          \
    asm volatile("ldmatrix.sync.aligned.m8n8.x4.shared.b16 {%0,%1,%2,%3}, [%4];" \
                 : "=r"(r0), "=r"(r1), "=r"(r2), "=r"(r3) : "r"(addr))

#define LDM_X4T(r0, r1, r2, r3, addr)                                         \
    asm volatile("ldmatrix.sync.aligned.m8n8.x4.trans.shared.b16 {%0,%1,%2,%3}, [%4];" \
                 : "=r"(r0), "=r"(r1), "=r"(r2), "=r"(r3) : "r"(addr))

#define MMA_BF16(d, a, b)                                                     \
    asm volatile("mma.sync.aligned.m16n8k16.row.col.f32.bf16.bf16.f32 "       \
                 "{%0,%1,%2,%3}, {%4,%5,%6,%7}, {%8,%9}, {%0,%1,%2,%3};"      \
                 : "+f"((d)[0]), "+f"((d)[1]), "+f"((d)[2]), "+f"((d)[3])     \
                 : "r"((a)[0]), "r"((a)[1]), "r"((a)[2]), "r"((a)[3]),        \
                   "r"((b)[0]), "r"((b)[1]))

__device__ __forceinline__ uint32_t pack_bf16(float lo, float hi) {
    uint32_t r;
    asm("cvt.rn.bf16x2.f32 %0, %1, %2;" : "=r"(r) : "f"(hi), "f"(lo));
    return r;
}
__device__ __forceinline__ float2 unpack_bf16(uint32_t v) {
    __nv_bfloat162 h = *reinterpret_cast<__nv_bfloat162*>(&v);
    return __bfloat1622float2(h);
}

// ---------------------------------------------------------------------------
// fp32 -> bf16 hi/lo split
// ---------------------------------------------------------------------------
__global__ void cvt_hilo(const float* __restrict__ src,
                         __nv_bfloat16* __restrict__ hi,
                         __nv_bfloat16* __restrict__ lo, int n4) {
    int i = blockIdx.x * blockDim.x + threadIdx.x;
    if (i >= n4) return;
    float4 v = ((const float4*)src)[i];
    uint32_t h01 = pack_bf16(v.x, v.y);
    uint32_t h23 = pack_bf16(v.z, v.w);
    float2 b01 = unpack_bf16(h01);
    float2 b23 = unpack_bf16(h23);
    uint32_t l01 = pack_bf16(v.x - b01.x, v.y - b01.y);
    uint32_t l23 = pack_bf16(v.z - b23.x, v.w - b23.y);
    ((uint2*)hi)[i] = make_uint2(h01, h23);
    ((uint2*)lo)[i] = make_uint2(l01, l23);
}

// ---------------------------------------------------------------------------
// mma.sync bf16 GEMM, hi/lo 3-term split.
// CTA tile 256x128, BK=32, 8 warps (4m x 2n), warp tile 64x64.
// 3-stage cp.async pipeline. smem row stride 80B (64B data + 16 pad).
// Epilogue MODE: 0 = fp32 C; 1 = bf16 hi/lo split; 2 = RoPE + scale + split.
// ---------------------------------------------------------------------------
#define GA_TILE (256 * 80)           // A hi or lo: 20480 B
#define GB_TILE (128 * 80)           // B hi or lo: 10240 B
#define G_STAGE (2 * GA_TILE + 2 * GB_TILE)   // 61440 B
#define GEMM_SMEM (3 * G_STAGE)               // 184320 B

template <int MODE>
__global__ __launch_bounds__(256, 1)
void gemm_mma(const __nv_bfloat16* __restrict__ Ah, const __nv_bfloat16* __restrict__ Al,
              const __nv_bfloat16* __restrict__ Bh, const __nv_bfloat16* __restrict__ Bl,
              float* __restrict__ C,
              __nv_bfloat16* __restrict__ Oh, __nv_bfloat16* __restrict__ Ol,
              const float* __restrict__ cosv, const float* __restrict__ sinv,
              float scale, int Mn, int Nn, int Kn) {
    extern __shared__ char smem[];
    const uint32_t sb = smem_u32(smem);

    const int tid = threadIdx.x;
    const int lane = tid & 31;
    const int wid = tid >> 5;
    const int wm = wid >> 1;        // 0..3 -> m offset wm*64
    const int wn = wid & 1;         // 0..1 -> n offset wn*64
    const int m0 = blockIdx.y * 256;
    const int n0 = blockIdx.x * 128;
    const int NS = Kn / 32;

    // cp.async mapping
    // A: 1024 chunks of 16B per matrix -> 4 per thread; B: 512 -> 2 per thread.
    int arow[4], acc_[4];
    uint32_t asoff[4];
#pragma unroll
    for (int i = 0; i < 4; i++) {
        int c = tid + i * 256;
        arow[i] = c >> 2; acc_[i] = c & 3;
        asoff[i] = arow[i] * 80 + acc_[i] * 16;
    }
    int brow[2], bcc[2];
    uint32_t bsoff[2];
#pragma unroll
    for (int i = 0; i < 2; i++) {
        int c = tid + i * 256;
        brow[i] = c >> 2; bcc[i] = c & 3;
        bsoff[i] = brow[i] * 80 + bcc[i] * 16;
    }

#define LOAD_STAGE(j)                                                         \
    do {                                                                      \
        const uint32_t _b = sb + ((j) % 3) * G_STAGE;                         \
        const int _kg = (j) * 32;                                             \
        _Pragma("unroll")                                                     \
        for (int i = 0; i < 4; i++) {                                         \
            size_t off = (size_t)(m0 + arow[i]) * Kn + _kg + acc_[i] * 8;     \
            CP16(_b + asoff[i],           Ah + off);                          \
            CP16(_b + GA_TILE + asoff[i], Al + off);                          \
        }                                                                     \
        _Pragma("unroll")                                                     \
        for (int i = 0; i < 2; i++) {                                         \
            size_t off = (size_t)(n0 + brow[i]) * Kn + _kg + bcc[i] * 8;      \
            CP16(_b + 2 * GA_TILE + bsoff[i],           Bh + off);            \
            CP16(_b + 2 * GA_TILE + GB_TILE + bsoff[i], Bl + off);            \
        }                                                                     \
        CP_COMMIT();                                                          \
    } while (0)

    const uint32_t aoff = (uint32_t)((wm * 64 + (lane & 15)) * 80 + (lane >> 4) * 16);
    const uint32_t boff = (uint32_t)((wn * 64 + (lane >> 4) * 8 + (lane & 7)) * 80 +
                                     ((lane >> 3) & 1) * 16);

    float acc[4][8][4];
#pragma unroll
    for (int mt = 0; mt < 4; mt++)
#pragma unroll
        for (int nt = 0; nt < 8; nt++)
#pragma unroll
            for (int q = 0; q < 4; q++) acc[mt][nt][q] = 0.f;

    LOAD_STAGE(0);
    LOAD_STAGE(1);

    for (int i = 0; i < NS; i++) {
        if (i + 2 < NS) { LOAD_STAGE(i + 2); CP_WAIT(2); }
        else if (i + 1 < NS) { CP_WAIT(1); }
        else { CP_WAIT(0); }
        __syncthreads();

        const uint32_t base = sb + (i % 3) * G_STAGE;
        const uint32_t sAh = base + aoff;
        const uint32_t sAl = base + GA_TILE + aoff;
        const uint32_t sBh = base + 2 * GA_TILE + boff;
        const uint32_t sBl = base + 2 * GA_TILE + GB_TILE + boff;

#pragma unroll
        for (int k0 = 0; k0 < 2; k0++) {
            const uint32_t kb = k0 * 32;
            uint32_t ah[4][4], al[4][4];
#pragma unroll
            for (int mt = 0; mt < 4; mt++) {
                LDM_X4(ah[mt][0], ah[mt][1], ah[mt][2], ah[mt][3],
                       sAh + mt * (16 * 80) + kb);
                LDM_X4(al[mt][0], al[mt][1], al[mt][2], al[mt][3],
                       sAl + mt * (16 * 80) + kb);
            }
#pragma unroll
            for (int half = 0; half < 2; half++) {
                uint32_t bh[4][2], bl[4][2];
#pragma unroll
                for (int j = 0; j < 2; j++) {
                    uint32_t r0, r1, r2, r3;
                    LDM_X4(r0, r1, r2, r3,
                           sBh + (half * 2 + j) * (16 * 80) + kb);
                    bh[j * 2][0] = r0; bh[j * 2][1] = r1;
                    bh[j * 2 + 1][0] = r2; bh[j * 2 + 1][1] = r3;
                    LDM_X4(r0, r1, r2, r3,
                           sBl + (half * 2 + j) * (16 * 80) + kb);
                    bl[j * 2][0] = r0; bl[j * 2][1] = r1;
                    bl[j * 2 + 1][0] = r2; bl[j * 2 + 1][1] = r3;
                }
#pragma unroll
                for (int mt = 0; mt < 4; mt++)
#pragma unroll
                    for (int ntl = 0; ntl < 4; ntl++) {
                        float* d = acc[mt][half * 4 + ntl];
                        MMA_BF16(d, ah[mt], bh[ntl]);
                        MMA_BF16(d, ah[mt], bl[ntl]);
                        MMA_BF16(d, al[mt], bh[ntl]);
                    }
            }
        }
        __syncthreads();
    }
#undef LOAD_STAGE

    // ---- epilogue
#pragma unroll
    for (int mt = 0; mt < 4; mt++) {
        const int row = m0 + wm * 64 + mt * 16 + (lane >> 2);
#pragma unroll
        for (int nt = 0; nt < 8; nt++) {
            const int col = n0 + wn * 64 + nt * 8 + (lane & 3) * 2;
            float f0 = acc[mt][nt][0], f1 = acc[mt][nt][1];
            float f2 = acc[mt][nt][2], f3 = acc[mt][nt][3];
            if (MODE == 0) {
                *(float2*)&C[(size_t)row * Nn + col] = make_float2(f0, f1);
                *(float2*)&C[(size_t)(row + 8) * Nn + col] = make_float2(f2, f3);
            } else {
                if (MODE == 2) {
                    const int i2 = (col & 127) >> 1;
                    const int t0r = row & (T_ - 1);
                    const int t1r = (row + 8) & (T_ - 1);
                    float c0 = cosv[t0r * 64 + i2], s0 = sinv[t0r * 64 + i2];
                    float c1 = cosv[t1r * 64 + i2], s1 = sinv[t1r * 64 + i2];
                    float r0 = f0 * c0 - f1 * s0, r1 = f0 * s0 + f1 * c0;
                    float r2 = f2 * c1 - f3 * s1, r3 = f2 * s1 + f3 * c1;
                    f0 = r0 * scale; f1 = r1 * scale;
                    f2 = r2 * scale; f3 = r3 * scale;
                }
                uint32_t h01 = pack_bf16(f0, f1);
                uint32_t h23 = pack_bf16(f2, f3);
                float2 b01 = unpack_bf16(h01);
                float2 b23 = unpack_bf16(h23);
                uint32_t l01 = pack_bf16(f0 - b01.x, f1 - b01.y);
                uint32_t l23 = pack_bf16(f2 - b23.x, f3 - b23.y);
                *(uint32_t*)(Oh + (size_t)row * Nn + col) = h01;
                *(uint32_t*)(Ol + (size_t)row * Nn + col) = l01;
                *(uint32_t*)(Oh + (size_t)(row + 8) * Nn + col) = h23;
                *(uint32_t*)(Ol + (size_t)(row + 8) * Nn + col) = l23;
            }
        }
    }
}

// ---------------------------------------------------------------------------
// Tensor-core flash attention, bf16 hi/lo split throughout (unchanged R7).
// ---------------------------------------------------------------------------
#define AT_QB    34816
#define AT_KVT   17408
#define AT_STAGEB (4 * AT_KVT)
#define ATTN_SMEM (2 * AT_QB + 2 * AT_STAGEB)

__global__ __launch_bounds__(256, 1)
void attn_mma(const __nv_bfloat16* __restrict__ qh, const __nv_bfloat16* __restrict__ ql,
              const __nv_bfloat16* __restrict__ kh, const __nv_bfloat16* __restrict__ kl,
              const __nv_bfloat16* __restrict__ vh, const __nv_bfloat16* __restrict__ vl,
              __nv_bfloat16* __restrict__ oh, __nv_bfloat16* __restrict__ ol) {
    extern __shared__ char smem[];
    const uint32_t sb = smem_u32(smem);
    const int tid = threadIdx.x;
    const int lane = tid & 31;
    const int wid = tid >> 5;
    const int qt0 = blockIdx.x * 128;
    const int h = blockIdx.y;
    const int b = blockIdx.z;
    const int bT = b * T_;
    const size_t headcol = (size_t)h * HD_;

#pragma unroll
    for (int it = 0; it < 8; it++) {
        int x = tid + it * 256;
        int row = x >> 4, c = x & 15;
        size_t g = (size_t)(bT + qt0 + row) * EMB_ + headcol + c * 8;
        CP16(sb + row * 272 + c * 16, qh + g);
        CP16(sb + AT_QB + row * 272 + c * 16, ql + g);
    }

#define AT_STAGE(j)                                                            \
    do {                                                                       \
        const uint32_t bs_ = sb + 2 * AT_QB + ((j) & 1) * AT_STAGEB;           \
        const int kt_ = (j) * 64;                                              \
        _Pragma("unroll")                                                      \
        for (int it = 0; it < 16; it++) {                                      \
            int x = tid + it * 256;                                            \
            int tsel = x >> 10;                                                \
            int w = x & 1023;                                                  \
            int row = w >> 4, c = w & 15;                                      \
            size_t g = (size_t)(bT + kt_ + row) * EMB_ + headcol + c * 8;      \
            const __nv_bfloat16* p = (tsel == 0) ? kh : (tsel == 1) ? kl       \
                                   : (tsel == 2) ? vh : vl;                    \
            CP16(bs_ + tsel * AT_KVT + row * 272 + c * 16, p + g);             \
        }                                                                      \
        CP_COMMIT();                                                           \
    } while (0)

    AT_STAGE(0);

    const uint32_t aoff = (uint32_t)((wid * 16 + (lane & 15)) * 272 + (lane >> 4) * 16);
    const uint32_t koff = (uint32_t)(((lane >> 4) * 8 + (lane & 7)) * 272 +
                                     ((lane >> 3) & 1) * 16);
    const uint32_t voff = (uint32_t)((((lane >> 3) & 1) * 8 + (lane & 7)) * 272 +
                                     (lane >> 4) * 16);

    float acc_o[16][4];
#pragma unroll
    for (int nt = 0; nt < 16; nt++)
#pragma unroll
        for (int q = 0; q < 4; q++) acc_o[nt][q] = 0.f;
    float m0 = -CUDART_INF_F, m1 = -CUDART_INF_F;
    float l0 = 0.f, l1 = 0.f;

    for (int it = 0; it < T_ / 64; it++) {
        if (it + 1 < T_ / 64) { AT_STAGE(it + 1); CP_WAIT(1); }
        else                  { CP_WAIT(0); }
        __syncthreads();

        const uint32_t bs = sb + 2 * AT_QB + (it & 1) * AT_STAGEB;

        float accs[8][4];
#pragma unroll
        for (int nt = 0; nt < 8; nt++)
#pragma unroll
            for (int q = 0; q < 4; q++) accs[nt][q] = 0.f;

#pragma unroll
        for (int ks = 0; ks < 8; ks++) {
            uint32_t aH[4], aL[4];
            LDM_X4(aH[0], aH[1], aH[2], aH[3], sb + aoff + ks * 32);
            LDM_X4(aL[0], aL[1], aL[2], aL[3], sb + AT_QB + aoff + ks * 32);
#pragma unroll
            for (int jn = 0; jn < 4; jn++) {
                uint32_t r0, r1, r2, r3;
                uint32_t bH[2][2], bL[2][2];
                LDM_X4(r0, r1, r2, r3, bs + jn * (16 * 272) + koff + ks * 32);
                bH[0][0] = r0; bH[0][1] = r1; bH[1][0] = r2; bH[1][1] = r3;
                LDM_X4(r0, r1, r2, r3, bs + AT_KVT + jn * (16 * 272) + koff + ks * 32);
                bL[0][0] = r0; bL[0][1] = r1; bL[1][0] = r2; bL[1][1] = r3;
#pragma unroll
                for (int q = 0; q < 2; q++) {
                    MMA_BF16(accs[jn * 2 + q], aH, bH[q]);
                    MMA_BF16(accs[jn * 2 + q], aH, bL[q]);
                    MMA_BF16(accs[jn * 2 + q], aL, bH[q]);
                }
            }
        }

        float rm0 = accs[0][0], rm1 = accs[0][2];
#pragma unroll
        for (int nt = 0; nt < 8; nt++) {
            rm0 = fmaxf(rm0, fmaxf(accs[nt][0], accs[nt][1]));
            rm1 = fmaxf(rm1, fmaxf(accs[nt][2], accs[nt][3]));
        }
        rm0 = fmaxf(rm0, __shfl_xor_sync(0xffffffffu, rm0, 1));
        rm0 = fmaxf(rm0, __shfl_xor_sync(0xffffffffu, rm0, 2));
        rm1 = fmaxf(rm1, __shfl_xor_sync(0xffffffffu, rm1, 1));
        rm1 = fmaxf(rm1, __shfl_xor_sync(0xffffffffu, rm1, 2));

        float mn0 = fmaxf(m0, rm0);
        float mn1 = fmaxf(m1, rm1);
        float al0 = __expf(m0 - mn0);
        float al1 = __expf(m1 - mn1);
        m0 = mn0; m1 = mn1;

        float rs0 = 0.f, rs1 = 0.f;
#pragma unroll
        for (int nt = 0; nt < 8; nt++) {
            accs[nt][0] = __expf(accs[nt][0] - m0);
            accs[nt][1] = __expf(accs[nt][1] - m0);
            accs[nt][2] = __expf(accs[nt][2] - m1);
            accs[nt][3] = __expf(accs[nt][3] - m1);
            rs0 += accs[nt][0] + accs[nt][1];
            rs1 += accs[nt][2] + accs[nt][3];
        }
        rs0 += __shfl_xor_sync(0xffffffffu, rs0, 1);
        rs0 += __shfl_xor_sync(0xffffffffu, rs0, 2);
        rs1 += __shfl_xor_sync(0xffffffffu, rs1, 1);
        rs1 += __shfl_xor_sync(0xffffffffu, rs1, 2);
        l0 = l0 * al0 + rs0;
        l1 = l1 * al1 + rs1;

#pragma unroll
        for (int nt = 0; nt < 16; nt++) {
            acc_o[nt][0] *= al0;
            acc_o[nt][1] *= al0;
            acc_o[nt][2] *= al1;
            acc_o[nt][3] *= al1;
        }

        uint32_t aPh[4][4], aPl[4][4];
#pragma unroll
        for (int ks2 = 0; ks2 < 4; ks2++) {
#pragma unroll
            for (int half = 0; half < 2; half++) {
                int nt = ks2 * 2 + half;
                uint32_t h01 = pack_bf16(accs[nt][0], accs[nt][1]);
                uint32_t h23 = pack_bf16(accs[nt][2], accs[nt][3]);
                float2 b01 = unpack_bf16(h01);
                float2 b23 = unpack_bf16(h23);
                uint32_t l01 = pack_bf16(accs[nt][0] - b01.x, accs[nt][1] - b01.y);
                uint32_t l23 = pack_bf16(accs[nt][2] - b23.x, accs[nt][3] - b23.y);
                aPh[ks2][half * 2]     = h01;
                aPh[ks2][half * 2 + 1] = h23;
                aPl[ks2][half * 2]     = l01;
                aPl[ks2][half * 2 + 1] = l23;
            }
        }

        const uint32_t vbh = bs + 2 * AT_KVT + voff;
        const uint32_t vbl = bs + 3 * AT_KVT + voff;
#pragma unroll
        for (int ks2 = 0; ks2 < 4; ks2++) {
#pragma unroll
            for (int j = 0; j < 8; j++) {
                uint32_t r0, r1, r2, r3;
                uint32_t bv[2][2], bw[2][2];
                LDM_X4T(r0, r1, r2, r3, vbh + ks2 * (16 * 272) + j * 32);
                bv[0][0] = r0; bv[0][1] = r1; bv[1][0] = r2; bv[1][1] = r3;
                LDM_X4T(r0, r1, r2, r3, vbl + ks2 * (16 * 272) + j * 32);
                bw[0][0] = r0; bw[0][1] = r1; bw[1][0] = r2; bw[1][1] = r3;
#pragma unroll
                for (int q = 0; q < 2; q++) {
                    MMA_BF16(acc_o[j * 2 + q], aPh[ks2], bv[q]);
                    MMA_BF16(acc_o[j * 2 + q], aPh[ks2], bw[q]);
                    MMA_BF16(acc_o[j * 2 + q], aPl[ks2], bv[q]);
                }
            }
        }
        __syncthreads();
    }
#undef AT_STAGE

    const float inv0 = 1.f / l0;
    const float inv1 = 1.f / l1;
    const size_t gr0 = (size_t)(bT + qt0 + wid * 16 + (lane >> 2)) * EMB_ +
                       headcol + (lane & 3) * 2;
    const size_t gr1 = gr0 + 8 * EMB_;
#pragma unroll
    for (int nt = 0; nt < 16; nt++) {
        float f0 = acc_o[nt][0] * inv0, f1 = acc_o[nt][1] * inv0;
        float f2 = acc_o[nt][2] * inv1, f3 = acc_o[nt][3] * inv1;
        uint32_t h01 = pack_bf16(f0, f1);
        uint32_t h23 = pack_bf16(f2, f3);
        float2 b01 = unpack_bf16(h01);
        float2 b23 = unpack_bf16(h23);
        uint32_t l01 = pack_bf16(f0 - b01.x, f1 - b01.y);
        uint32_t l23 = pack_bf16(f2 - b23.x, f3 - b23.y);
        *(uint32_t*)(oh + gr0 + nt * 8) = h01;
        *(uint32_t*)(ol + gr0 + nt * 8) = l01;
        *(uint32_t*)(oh + gr1 + nt * 8) = h23;
        *(uint32_t*)(ol + gr1 + nt * 8) = l23;
    }
}

// ---------------------------------------------------------------------------
extern "C" void kernel_launch(void* const* d_in, const int* in_sizes, int n_in,
                              void* d_out, int out_size) {
    const float* x    = (const float*)d_in[0];
    const float* wq   = (const float*)d_in[1];
    const float* wk   = (const float*)d_in[2];
    const float* wv   = (const float*)d_in[3];
    const float* wo   = (const float*)d_in[4];
    const float* fcos = (const float*)d_in[7];
    const float* fsin = (const float*)d_in[8];
    float* out = (float*)d_out;

    __nv_bfloat16 *gxh, *gxl, *gwh, *gwl, *gah, *gal;
    __nv_bfloat16 *gqh, *gql, *gkh, *gkl, *gvh, *gvl;
    cudaGetSymbolAddress((void**)&gxh, g_xh);
    cudaGetSymbolAddress((void**)&gxl, g_xl);
    cudaGetSymbolAddress((void**)&gwh, g_wh);
    cudaGetSymbolAddress((void**)&gwl, g_wl);
    cudaGetSymbolAddress((void**)&gah, g_ah);
    cudaGetSymbolAddress((void**)&gal, g_al);
    cudaGetSymbolAddress((void**)&gqh, g_qh);
    cudaGetSymbolAddress((void**)&gql, g_ql);
    cudaGetSymbolAddress((void**)&gkh, g_kh);
    cudaGetSymbolAddress((void**)&gkl, g_kl);
    cudaGetSymbolAddress((void**)&gvh, g_vh);
    cudaGetSymbolAddress((void**)&gvl, g_vl);

    cudaFuncSetAttribute(gemm_mma<0>,
                         cudaFuncAttributeMaxDynamicSharedMemorySize, GEMM_SMEM);
    cudaFuncSetAttribute(gemm_mma<1>,
                         cudaFuncAttributeMaxDynamicSharedMemorySize, GEMM_SMEM);
    cudaFuncSetAttribute(gemm_mma<2>,
                         cudaFuncAttributeMaxDynamicSharedMemorySize, GEMM_SMEM);
    cudaFuncSetAttribute(attn_mma,
                         cudaFuncAttributeMaxDynamicSharedMemorySize, ATTN_SMEM);

    const size_t WSZ = (size_t)EMB_ * EMB_;
    const int n4x = (M_ * EMB_) / 4;
    const int n4w = (EMB_ * EMB_) / 4;
    const float qsc = 0.08838834764831845f;   // 1/sqrt(128)

    cvt_hilo<<<(n4x + 255) / 256, 256>>>(x, gxh, gxl, n4x);
    cvt_hilo<<<(n4w + 255) / 256, 256>>>(wq, gwh + 0 * WSZ, gwl + 0 * WSZ, n4w);
    cvt_hilo<<<(n4w + 255) / 256, 256>>>(wk, gwh + 1 * WSZ, gwl + 1 * WSZ, n4w);
    cvt_hilo<<<(n4w + 255) / 256, 256>>>(wv, gwh + 2 * WSZ, gwl + 2 * WSZ, n4w);
    cvt_hilo<<<(n4w + 255) / 256, 256>>>(wo, gwh + 3 * WSZ, gwl + 3 * WSZ, n4w);

    dim3 ggrid(EMB_ / 128, M_ / 256);
    // Q: RoPE + scale + split
    gemm_mma<2><<<ggrid, 256, GEMM_SMEM>>>(gxh, gxl, gwh + 0 * WSZ, gwl + 0 * WSZ,
                                           nullptr, gqh, gql, fcos, fsin, qsc,
                                           M_, EMB_, EMB_);
    // K: RoPE + split
    gemm_mma<2><<<ggrid, 256, GEMM_SMEM>>>(gxh, gxl, gwh + 1 * WSZ, gwl + 1 * WSZ,
                                           nullptr, gkh, gkl, fcos, fsin, 1.0f,
                                           M_, EMB_, EMB_);
    // V: plain split
    gemm_mma<1><<<ggrid, 256, GEMM_SMEM>>>(gxh, gxl, gwh + 2 * WSZ, gwl + 2 * WSZ,
                                           nullptr, gvh, gvl, nullptr, nullptr, 1.0f,
                                           M_, EMB_, EMB_);

    dim3 agrid(T_ / 128, H_, B_);
    attn_mma<<<agrid, 256, ATTN_SMEM>>>(gqh, gql, gkh, gkl, gvh, gvl, gah, gal);

    // out projection: fp32 output
    gemm_mma<0><<<ggrid, 256, GEMM_SMEM>>>(gah, gal, gwh + 3 * WSZ, gwl + 3 * WSZ,
                                           out, nullptr, nullptr, nullptr, nullptr,
                                           1.0f, M_, EMB_, EMB_);
}

// round 13
// speedup vs baseline: 4.0076x; 1.3567x over previous
#include <cuda_runtime.h>
#include <cuda_fp16.h>
#include <math_constants.h>
#include <cstdint>

#define B_   2
#define T_   2048
#define EMB_ 2048
#define H_   16
#define HD_  128
#define M_   (B_ * T_)   // 4096

// ---------------------------------------------------------------------------
// Scratch (__device__ globals; no allocation allowed)
// ---------------------------------------------------------------------------
__device__ __half g_xh[(size_t)M_ * EMB_];
__device__ __half g_xl[(size_t)M_ * EMB_];
__device__ __half g_wh[4][(size_t)EMB_ * EMB_];
__device__ __half g_ah[(size_t)M_ * EMB_];
__device__ __half g_al[(size_t)M_ * EMB_];
__device__ __half g_qh[(size_t)M_ * EMB_];
__device__ __half g_ql[(size_t)M_ * EMB_];
__device__ __half g_kh[(size_t)M_ * EMB_];
__device__ __half g_vh[(size_t)M_ * EMB_];

// ---------------------------------------------------------------------------
// helpers
// ---------------------------------------------------------------------------
__device__ __forceinline__ uint32_t smem_u32(const void* p) {
    uint32_t a;
    asm("{ .reg .u64 t; cvta.to.shared.u64 t, %1; cvt.u32.u64 %0, t; }"
        : "=r"(a) : "l"(p));
    return a;
}
#define CP16(dst, src) \
    asm volatile("cp.async.cg.shared.global [%0], [%1], 16;" \
                 :: "r"(dst), "l"(src))
#define CP_COMMIT() asm volatile("cp.async.commit_group;" ::: "memory")
#define CP_WAIT(n)  asm volatile("cp.async.wait_group %0;" :: "n"(n) : "memory")

#define LDM_X4(r0, r1, r2, r3, addr)                                          \
    asm volatile("ldmatrix.sync.aligned.m8n8.x4.shared.b16 {%0,%1,%2,%3}, [%4];" \
                 : "=r"(r0), "=r"(r1), "=r"(r2), "=r"(r3) : "r"(addr))

#define LDM_X4T(r0, r1, r2, r3, addr)                                         \
    asm volatile("ldmatrix.sync.aligned.m8n8.x4.trans.shared.b16 {%0,%1,%2,%3}, [%4];" \
                 : "=r"(r0), "=r"(r1), "=r"(r2), "=r"(r3) : "r"(addr))

#define MMA_F16(d, a, b)                                                      \
    asm volatile("mma.sync.aligned.m16n8k16.row.col.f32.f16.f16.f32 "         \
                 "{%0,%1,%2,%3}, {%4,%5,%6,%7}, {%8,%9}, {%0,%1,%2,%3};"      \
                 : "+f"((d)[0]), "+f"((d)[1]), "+f"((d)[2]), "+f"((d)[3])     \
                 : "r"((a)[0]), "r"((a)[1]), "r"((a)[2]), "r"((a)[3]),        \
                   "r"((b)[0]), "r"((b)[1]))

__device__ __forceinline__ uint32_t pack_f16(float lo, float hi) {
    uint32_t r;
    asm("cvt.rn.f16x2.f32 %0, %1, %2;" : "=r"(r) : "f"(hi), "f"(lo));
    return r;
}
__device__ __forceinline__ float2 unpack_f16(uint32_t v) {
    __half2 h = *reinterpret_cast<__half2*>(&v);
    return __half22float2(h);
}

// ---------------------------------------------------------------------------
// conversions
// ---------------------------------------------------------------------------
__global__ void cvt_split_f16(const float* __restrict__ src,
                              __half* __restrict__ hi,
                              __half* __restrict__ lo, int n4) {
    int i = blockIdx.x * blockDim.x + threadIdx.x;
    if (i >= n4) return;
    float4 v = ((const float4*)src)[i];
    uint32_t h01 = pack_f16(v.x, v.y);
    uint32_t h23 = pack_f16(v.z, v.w);
    float2 b01 = unpack_f16(h01);
    float2 b23 = unpack_f16(h23);
    uint32_t l01 = pack_f16(v.x - b01.x, v.y - b01.y);
    uint32_t l23 = pack_f16(v.z - b23.x, v.w - b23.y);
    ((uint2*)hi)[i] = make_uint2(h01, h23);
    ((uint2*)lo)[i] = make_uint2(l01, l23);
}

__global__ void cvt_f16(const float* __restrict__ src,
                        __half* __restrict__ dst, int n4) {
    int i = blockIdx.x * blockDim.x + threadIdx.x;
    if (i >= n4) return;
    float4 v = ((const float4*)src)[i];
    ((uint2*)dst)[i] = make_uint2(pack_f16(v.x, v.y), pack_f16(v.z, v.w));
}

// ---------------------------------------------------------------------------
// mma.sync fp16 GEMM, 2-term A-split: C = (Ah + Al) * Bh^T
// CTA tile 256x128, BK=32, 8 warps (4m x 2n), warp tile 64x64.
// 4-stage cp.async pipeline. smem row stride 80B.
// MODE: 0 = fp32 C; 1 = f16 hi (+lo if Ol); 2 = RoPE then f16 hi (+lo if Ol).
// ---------------------------------------------------------------------------
#define GA_TILE (256 * 80)                    // 20480 B
#define GB_TILE (128 * 80)                    // 10240 B
#define G_STAGE (2 * GA_TILE + GB_TILE)       // 51200 B
#define GEMM_SMEM (4 * G_STAGE)               // 204800 B

template <int MODE>
__global__ __launch_bounds__(256, 1)
void gemm_f16(const __half* __restrict__ Ah, const __half* __restrict__ Al,
              const __half* __restrict__ Bh,
              float* __restrict__ C,
              __half* __restrict__ Oh, __half* __restrict__ Ol,
              const float* __restrict__ cosv, const float* __restrict__ sinv,
              int Mn, int Nn, int Kn) {
    extern __shared__ char smem[];
    const uint32_t sb = smem_u32(smem);

    const int tid = threadIdx.x;
    const int lane = tid & 31;
    const int wid = tid >> 5;
    const int wm = wid >> 1;
    const int wn = wid & 1;
    const int m0 = blockIdx.y * 256;
    const int n0 = blockIdx.x * 128;
    const int NS = Kn / 32;

    int arow[4], acc_[4];
    uint32_t asoff[4];
#pragma unroll
    for (int i = 0; i < 4; i++) {
        int c = tid + i * 256;
        arow[i] = c >> 2; acc_[i] = c & 3;
        asoff[i] = arow[i] * 80 + acc_[i] * 16;
    }
    int brow[2], bcc[2];
    uint32_t bsoff[2];
#pragma unroll
    for (int i = 0; i < 2; i++) {
        int c = tid + i * 256;
        brow[i] = c >> 2; bcc[i] = c & 3;
        bsoff[i] = brow[i] * 80 + bcc[i] * 16;
    }

#define LOAD_STAGE(j)                                                         \
    do {                                                                      \
        const uint32_t _b = sb + ((j) & 3) * G_STAGE;                         \
        const int _kg = (j) * 32;                                             \
        _Pragma("unroll")                                                     \
        for (int i = 0; i < 4; i++) {                                         \
            size_t off = (size_t)(m0 + arow[i]) * Kn + _kg + acc_[i] * 8;     \
            CP16(_b + asoff[i],           Ah + off);                          \
            CP16(_b + GA_TILE + asoff[i], Al + off);                          \
        }                                                                     \
        _Pragma("unroll")                                                     \
        for (int i = 0; i < 2; i++) {                                         \
            size_t off = (size_t)(n0 + brow[i]) * Kn + _kg + bcc[i] * 8;      \
            CP16(_b + 2 * GA_TILE + bsoff[i], Bh + off);                      \
        }                                                                     \
        CP_COMMIT();                                                          \
    } while (0)

    const uint32_t aoff = (uint32_t)((wm * 64 + (lane & 15)) * 80 + (lane >> 4) * 16);
    const uint32_t boff = (uint32_t)((wn * 64 + (lane >> 4) * 8 + (lane & 7)) * 80 +
                                     ((lane >> 3) & 1) * 16);

    float acc[4][8][4];
#pragma unroll
    for (int mt = 0; mt < 4; mt++)
#pragma unroll
        for (int nt = 0; nt < 8; nt++)
#pragma unroll
            for (int q = 0; q < 4; q++) acc[mt][nt][q] = 0.f;

    LOAD_STAGE(0);
    LOAD_STAGE(1);
    LOAD_STAGE(2);

    for (int i = 0; i < NS; i++) {
        if (i + 3 < NS)      { LOAD_STAGE(i + 3); CP_WAIT(3); }
        else if (i + 2 < NS) { CP_WAIT(2); }
        else if (i + 1 < NS) { CP_WAIT(1); }
        else                 { CP_WAIT(0); }
        __syncthreads();

        const uint32_t base = sb + (i & 3) * G_STAGE;
        const uint32_t sAh = base + aoff;
        const uint32_t sAl = base + GA_TILE + aoff;
        const uint32_t sBh = base + 2 * GA_TILE + boff;

#pragma unroll
        for (int k0 = 0; k0 < 2; k0++) {
            const uint32_t kb = k0 * 32;
            uint32_t ah[4][4], al[4][4];
#pragma unroll
            for (int mt = 0; mt < 4; mt++) {
                LDM_X4(ah[mt][0], ah[mt][1], ah[mt][2], ah[mt][3],
                       sAh + mt * (16 * 80) + kb);
                LDM_X4(al[mt][0], al[mt][1], al[mt][2], al[mt][3],
                       sAl + mt * (16 * 80) + kb);
            }
#pragma unroll
            for (int half = 0; half < 2; half++) {
                uint32_t bh[4][2];
#pragma unroll
                for (int j = 0; j < 2; j++) {
                    uint32_t r0, r1, r2, r3;
                    LDM_X4(r0, r1, r2, r3,
                           sBh + (half * 2 + j) * (16 * 80) + kb);
                    bh[j * 2][0] = r0; bh[j * 2][1] = r1;
                    bh[j * 2 + 1][0] = r2; bh[j * 2 + 1][1] = r3;
                }
#pragma unroll
                for (int mt = 0; mt < 4; mt++)
#pragma unroll
                    for (int ntl = 0; ntl < 4; ntl++) {
                        float* d = acc[mt][half * 4 + ntl];
                        MMA_F16(d, ah[mt], bh[ntl]);
                        MMA_F16(d, al[mt], bh[ntl]);
                    }
            }
        }
        __syncthreads();
    }
#undef LOAD_STAGE

    // ---- epilogue
#pragma unroll
    for (int mt = 0; mt < 4; mt++) {
        const int row = m0 + wm * 64 + mt * 16 + (lane >> 2);
#pragma unroll
        for (int nt = 0; nt < 8; nt++) {
            const int col = n0 + wn * 64 + nt * 8 + (lane & 3) * 2;
            float f0 = acc[mt][nt][0], f1 = acc[mt][nt][1];
            float f2 = acc[mt][nt][2], f3 = acc[mt][nt][3];
            if (MODE == 0) {
                *(float2*)&C[(size_t)row * Nn + col] = make_float2(f0, f1);
                *(float2*)&C[(size_t)(row + 8) * Nn + col] = make_float2(f2, f3);
            } else {
                if (MODE == 2) {
                    const int i2 = (col & 127) >> 1;
                    const int t0r = row & (T_ - 1);
                    const int t1r = (row + 8) & (T_ - 1);
                    float c0 = cosv[t0r * 64 + i2], s0 = sinv[t0r * 64 + i2];
                    float c1 = cosv[t1r * 64 + i2], s1 = sinv[t1r * 64 + i2];
                    float r0 = f0 * c0 - f1 * s0, r1 = f0 * s0 + f1 * c0;
                    float r2 = f2 * c1 - f3 * s1, r3 = f2 * s1 + f3 * c1;
                    f0 = r0; f1 = r1; f2 = r2; f3 = r3;
                }
                uint32_t h01 = pack_f16(f0, f1);
                uint32_t h23 = pack_f16(f2, f3);
                *(uint32_t*)(Oh + (size_t)row * Nn + col) = h01;
                *(uint32_t*)(Oh + (size_t)(row + 8) * Nn + col) = h23;
                if (Ol) {
                    float2 b01 = unpack_f16(h01);
                    float2 b23 = unpack_f16(h23);
                    uint32_t l01 = pack_f16(f0 - b01.x, f1 - b01.y);
                    uint32_t l23 = pack_f16(f2 - b23.x, f3 - b23.y);
                    *(uint32_t*)(Ol + (size_t)row * Nn + col) = l01;
                    *(uint32_t*)(Ol + (size_t)(row + 8) * Nn + col) = l23;
                }
            }
        }
    }
}

// ---------------------------------------------------------------------------
// Tensor-core flash attention, fp16 2-term (Q split, K 1-term; P split, V 1-term).
// Scale 1/sqrt(HD) applied in fp32 softmax. 4-stage K/V pipeline.
// smem: Qh+Ql (2x34816) + 4 stages x (Kh+Vh = 2x17408) = 208896 B.
// ---------------------------------------------------------------------------
#define AT_QB     34816
#define AT_KVT    17408
#define AT_STAGEB (2 * AT_KVT)
#define ATTN_SMEM (2 * AT_QB + 4 * AT_STAGEB)

__global__ __launch_bounds__(256, 1)
void attn_f16(const __half* __restrict__ qh, const __half* __restrict__ ql,
              const __half* __restrict__ kh, const __half* __restrict__ vh,
              __half* __restrict__ oh, __half* __restrict__ ol) {
    extern __shared__ char smem[];
    const uint32_t sb = smem_u32(smem);
    const int tid = threadIdx.x;
    const int lane = tid & 31;
    const int wid = tid >> 5;
    const int qt0 = blockIdx.x * 128;
    const int h = blockIdx.y;
    const int b = blockIdx.z;
    const int bT = b * T_;
    const size_t headcol = (size_t)h * HD_;

    // Q tiles (hi + lo)
#pragma unroll
    for (int it = 0; it < 8; it++) {
        int x = tid + it * 256;
        int row = x >> 4, c = x & 15;
        size_t g = (size_t)(bT + qt0 + row) * EMB_ + headcol + c * 8;
        CP16(sb + row * 272 + c * 16, qh + g);
        CP16(sb + AT_QB + row * 272 + c * 16, ql + g);
    }

#define AT_STAGE(j)                                                            \
    do {                                                                       \
        const uint32_t bs_ = sb + 2 * AT_QB + ((j) & 3) * AT_STAGEB;           \
        const int kt_ = (j) * 64;                                              \
        _Pragma("unroll")                                                      \
        for (int it = 0; it < 8; it++) {                                       \
            int x = tid + it * 256;                                            \
            int tsel = x >> 10;                                                \
            int w = x & 1023;                                                  \
            int row = w >> 4, c = w & 15;                                      \
            size_t g = (size_t)(bT + kt_ + row) * EMB_ + headcol + c * 8;      \
            const __half* p = (tsel == 0) ? kh : vh;                           \
            CP16(bs_ + tsel * AT_KVT + row * 272 + c * 16, p + g);             \
        }                                                                      \
        CP_COMMIT();                                                           \
    } while (0)

    AT_STAGE(0);
    AT_STAGE(1);
    AT_STAGE(2);

    const uint32_t aoff = (uint32_t)((wid * 16 + (lane & 15)) * 272 + (lane >> 4) * 16);
    const uint32_t koff = (uint32_t)(((lane >> 4) * 8 + (lane & 7)) * 272 +
                                     ((lane >> 3) & 1) * 16);
    const uint32_t voff = (uint32_t)((((lane >> 3) & 1) * 8 + (lane & 7)) * 272 +
                                     (lane >> 4) * 16);

    float acc_o[16][4];
#pragma unroll
    for (int nt = 0; nt < 16; nt++)
#pragma unroll
        for (int q = 0; q < 4; q++) acc_o[nt][q] = 0.f;
    float m0 = -CUDART_INF_F, m1 = -CUDART_INF_F;
    float l0 = 0.f, l1 = 0.f;
    const float sc = 0.08838834764831845f;   // 1/sqrt(128)

    const int NT = T_ / 64;
    for (int it = 0; it < NT; it++) {
        if (it + 3 < NT)      { AT_STAGE(it + 3); CP_WAIT(3); }
        else if (it + 2 < NT) { CP_WAIT(2); }
        else if (it + 1 < NT) { CP_WAIT(1); }
        else                  { CP_WAIT(0); }
        __syncthreads();

        const uint32_t bs = sb + 2 * AT_QB + (it & 3) * AT_STAGEB;

        float accs[8][4];
#pragma unroll
        for (int nt = 0; nt < 8; nt++)
#pragma unroll
            for (int q = 0; q < 4; q++) accs[nt][q] = 0.f;

#pragma unroll
        for (int ks = 0; ks < 8; ks++) {
            uint32_t aH[4], aL[4];
            LDM_X4(aH[0], aH[1], aH[2], aH[3], sb + aoff + ks * 32);
            LDM_X4(aL[0], aL[1], aL[2], aL[3], sb + AT_QB + aoff + ks * 32);
#pragma unroll
            for (int jn = 0; jn < 4; jn++) {
                uint32_t r0, r1, r2, r3;
                uint32_t bH[2][2];
                LDM_X4(r0, r1, r2, r3, bs + jn * (16 * 272) + koff + ks * 32);
                bH[0][0] = r0; bH[0][1] = r1; bH[1][0] = r2; bH[1][1] = r3;
#pragma unroll
                for (int q = 0; q < 2; q++) {
                    MMA_F16(accs[jn * 2 + q], aH, bH[q]);
                    MMA_F16(accs[jn * 2 + q], aL, bH[q]);
                }
            }
        }

        // scale (softmax temperature) in fp32
#pragma unroll
        for (int nt = 0; nt < 8; nt++) {
            accs[nt][0] *= sc; accs[nt][1] *= sc;
            accs[nt][2] *= sc; accs[nt][3] *= sc;
        }

        float rm0 = accs[0][0], rm1 = accs[0][2];
#pragma unroll
        for (int nt = 0; nt < 8; nt++) {
            rm0 = fmaxf(rm0, fmaxf(accs[nt][0], accs[nt][1]));
            rm1 = fmaxf(rm1, fmaxf(accs[nt][2], accs[nt][3]));
        }
        rm0 = fmaxf(rm0, __shfl_xor_sync(0xffffffffu, rm0, 1));
        rm0 = fmaxf(rm0, __shfl_xor_sync(0xffffffffu, rm0, 2));
        rm1 = fmaxf(rm1, __shfl_xor_sync(0xffffffffu, rm1, 1));
        rm1 = fmaxf(rm1, __shfl_xor_sync(0xffffffffu, rm1, 2));

        float mn0 = fmaxf(m0, rm0);
        float mn1 = fmaxf(m1, rm1);
        float al0 = __expf(m0 - mn0);
        float al1 = __expf(m1 - mn1);
        m0 = mn0; m1 = mn1;

        float rs0 = 0.f, rs1 = 0.f;
#pragma unroll
        for (int nt = 0; nt < 8; nt++) {
            accs[nt][0] = __expf(accs[nt][0] - m0);
            accs[nt][1] = __expf(accs[nt][1] - m0);
            accs[nt][2] = __expf(accs[nt][2] - m1);
            accs[nt][3] = __expf(accs[nt][3] - m1);
            rs0 += accs[nt][0] + accs[nt][1];
            rs1 += accs[nt][2] + accs[nt][3];
        }
        rs0 += __shfl_xor_sync(0xffffffffu, rs0, 1);
        rs0 += __shfl_xor_sync(0xffffffffu, rs0, 2);
        rs1 += __shfl_xor_sync(0xffffffffu, rs1, 1);
        rs1 += __shfl_xor_sync(0xffffffffu, rs1, 2);
        l0 = l0 * al0 + rs0;
        l1 = l1 * al1 + rs1;

#pragma unroll
        for (int nt = 0; nt < 16; nt++) {
            acc_o[nt][0] *= al0;
            acc_o[nt][1] *= al0;
            acc_o[nt][2] *= al1;
            acc_o[nt][3] *= al1;
        }

        // P fragments (fp16 hi/lo)
        uint32_t aPh[4][4], aPl[4][4];
#pragma unroll
        for (int ks2 = 0; ks2 < 4; ks2++) {
#pragma unroll
            for (int half = 0; half < 2; half++) {
                int nt = ks2 * 2 + half;
                uint32_t h01 = pack_f16(accs[nt][0], accs[nt][1]);
                uint32_t h23 = pack_f16(accs[nt][2], accs[nt][3]);
                float2 b01 = unpack_f16(h01);
                float2 b23 = unpack_f16(h23);
                uint32_t l01 = pack_f16(accs[nt][0] - b01.x, accs[nt][1] - b01.y);
                uint32_t l23 = pack_f16(accs[nt][2] - b23.x, accs[nt][3] - b23.y);
                aPh[ks2][half * 2]     = h01;
                aPh[ks2][half * 2 + 1] = h23;
                aPl[ks2][half * 2]     = l01;
                aPl[ks2][half * 2 + 1] = l23;
            }
        }

        const uint32_t vb = bs + AT_KVT + voff;
#pragma unroll
        for (int ks2 = 0; ks2 < 4; ks2++) {
#pragma unroll
            for (int j = 0; j < 8; j++) {
                uint32_t r0, r1, r2, r3;
                uint32_t bv[2][2];
                LDM_X4T(r0, r1, r2, r3, vb + ks2 * (16 * 272) + j * 32);
                bv[0][0] = r0; bv[0][1] = r1; bv[1][0] = r2; bv[1][1] = r3;
#pragma unroll
                for (int q = 0; q < 2; q++) {
                    MMA_F16(acc_o[j * 2 + q], aPh[ks2], bv[q]);
                    MMA_F16(acc_o[j * 2 + q], aPl[ks2], bv[q]);
                }
            }
        }
        __syncthreads();
    }
#undef AT_STAGE

    const float inv0 = 1.f / l0;
    const float inv1 = 1.f / l1;
    const size_t gr0 = (size_t)(bT + qt0 + wid * 16 + (lane >> 2)) * EMB_ +
                       headcol + (lane & 3) * 2;
    const size_t gr1 = gr0 + 8 * EMB_;
#pragma unroll
    for (int nt = 0; nt < 16; nt++) {
        float f0 = acc_o[nt][0] * inv0, f1 = acc_o[nt][1] * inv0;
        float f2 = acc_o[nt][2] * inv1, f3 = acc_o[nt][3] * inv1;
        uint32_t h01 = pack_f16(f0, f1);
        uint32_t h23 = pack_f16(f2, f3);
        float2 b01 = unpack_f16(h01);
        float2 b23 = unpack_f16(h23);
        uint32_t l01 = pack_f16(f0 - b01.x, f1 - b01.y);
        uint32_t l23 = pack_f16(f2 - b23.x, f3 - b23.y);
        *(uint32_t*)(oh + gr0 + nt * 8) = h01;
        *(uint32_t*)(ol + gr0 + nt * 8) = l01;
        *(uint32_t*)(oh + gr1 + nt * 8) = h23;
        *(uint32_t*)(ol + gr1 + nt * 8) = l23;
    }
}

// ---------------------------------------------------------------------------
extern "C" void kernel_launch(void* const* d_in, const int* in_sizes, int n_in,
                              void* d_out, int out_size) {
    const float* x    = (const float*)d_in[0];
    const float* wq   = (const float*)d_in[1];
    const float* wk   = (const float*)d_in[2];
    const float* wv   = (const float*)d_in[3];
    const float* wo   = (const float*)d_in[4];
    const float* fcos = (const float*)d_in[7];
    const float* fsin = (const float*)d_in[8];
    float* out = (float*)d_out;

    __half *gxh, *gxl, *gwh, *gah, *gal, *gqh, *gql, *gkh, *gvh;
    cudaGetSymbolAddress((void**)&gxh, g_xh);
    cudaGetSymbolAddress((void**)&gxl, g_xl);
    cudaGetSymbolAddress((void**)&gwh, g_wh);
    cudaGetSymbolAddress((void**)&gah, g_ah);
    cudaGetSymbolAddress((void**)&gal, g_al);
    cudaGetSymbolAddress((void**)&gqh, g_qh);
    cudaGetSymbolAddress((void**)&gql, g_ql);
    cudaGetSymbolAddress((void**)&gkh, g_kh);
    cudaGetSymbolAddress((void**)&gvh, g_vh);

    cudaFuncSetAttribute(gemm_f16<0>,
                         cudaFuncAttributeMaxDynamicSharedMemorySize, GEMM_SMEM);
    cudaFuncSetAttribute(gemm_f16<1>,
                         cudaFuncAttributeMaxDynamicSharedMemorySize, GEMM_SMEM);
    cudaFuncSetAttribute(gemm_f16<2>,
                         cudaFuncAttributeMaxDynamicSharedMemorySize, GEMM_SMEM);
    cudaFuncSetAttribute(attn_f16,
                         cudaFuncAttributeMaxDynamicSharedMemorySize, ATTN_SMEM);

    const size_t WSZ = (size_t)EMB_ * EMB_;
    const int n4x = (M_ * EMB_) / 4;
    const int n4w = (EMB_ * EMB_) / 4;

    cvt_split_f16<<<(n4x + 255) / 256, 256>>>(x, gxh, gxl, n4x);
    cvt_f16<<<(n4w + 255) / 256, 256>>>(wq, gwh + 0 * WSZ, n4w);
    cvt_f16<<<(n4w + 255) / 256, 256>>>(wk, gwh + 1 * WSZ, n4w);
    cvt_f16<<<(n4w + 255) / 256, 256>>>(wv, gwh + 2 * WSZ, n4w);
    cvt_f16<<<(n4w + 255) / 256, 256>>>(wo, gwh + 3 * WSZ, n4w);

    dim3 ggrid(EMB_ / 128, M_ / 256);
    // Q: RoPE, write hi+lo
    gemm_f16<2><<<ggrid, 256, GEMM_SMEM>>>(gxh, gxl, gwh + 0 * WSZ,
                                           nullptr, gqh, gql, fcos, fsin,
                                           M_, EMB_, EMB_);
    // K: RoPE, write hi only
    gemm_f16<2><<<ggrid, 256, GEMM_SMEM>>>(gxh, gxl, gwh + 1 * WSZ,
                                           nullptr, gkh, nullptr, fcos, fsin,
                                           M_, EMB_, EMB_);
    // V: write hi only
    gemm_f16<1><<<ggrid, 256, GEMM_SMEM>>>(gxh, gxl, gwh + 2 * WSZ,
                                           nullptr, gvh, nullptr, nullptr, nullptr,
                                           M_, EMB_, EMB_);

    dim3 agrid(T_ / 128, H_, B_);
    attn_f16<<<agrid, 256, ATTN_SMEM>>>(gqh, gql, gkh, gvh, gah, gal);

    // out projection: fp32 output
    gemm_f16<0><<<ggrid, 256, GEMM_SMEM>>>(gah, gal, gwh + 3 * WSZ,
                                           out, nullptr, nullptr, nullptr, nullptr,
                                           M_, EMB_, EMB_);
}

// round 14
// speedup vs baseline: 4.2943x; 1.0716x over previous
#include <cuda_runtime.h>
#include <cuda_fp16.h>
#include <math_constants.h>
#include <cstdint>

#define B_   2
#define T_   2048
#define EMB_ 2048
#define H_   16
#define HD_  128
#define M_   (B_ * T_)   // 4096

// ---------------------------------------------------------------------------
// Scratch (__device__ globals; no allocation allowed)
// ---------------------------------------------------------------------------
__device__ __half g_xh[(size_t)M_ * EMB_];
__device__ __half g_xl[(size_t)M_ * EMB_];
__device__ __half g_wh[4][(size_t)EMB_ * EMB_];   // slots 0,1,2 contiguous = fused QKV weight
__device__ __half g_ah[(size_t)M_ * EMB_];
__device__ __half g_al[(size_t)M_ * EMB_];
__device__ __half g_qh[(size_t)M_ * EMB_];
__device__ __half g_ql[(size_t)M_ * EMB_];
__device__ __half g_kh[(size_t)M_ * EMB_];
__device__ __half g_vh[(size_t)M_ * EMB_];

// ---------------------------------------------------------------------------
// helpers
// ---------------------------------------------------------------------------
__device__ __forceinline__ uint32_t smem_u32(const void* p) {
    uint32_t a;
    asm("{ .reg .u64 t; cvta.to.shared.u64 t, %1; cvt.u32.u64 %0, t; }"
        : "=r"(a) : "l"(p));
    return a;
}
#define CP16(dst, src) \
    asm volatile("cp.async.cg.shared.global [%0], [%1], 16;" \
                 :: "r"(dst), "l"(src))
#define CP_COMMIT() asm volatile("cp.async.commit_group;" ::: "memory")
#define CP_WAIT(n)  asm volatile("cp.async.wait_group %0;" :: "n"(n) : "memory")

#define LDM_X4(r0, r1, r2, r3, addr)                                          \
    asm volatile("ldmatrix.sync.aligned.m8n8.x4.shared.b16 {%0,%1,%2,%3}, [%4];" \
                 : "=r"(r0), "=r"(r1), "=r"(r2), "=r"(r3) : "r"(addr))

#define LDM_X4T(r0, r1, r2, r3, addr)                                         \
    asm volatile("ldmatrix.sync.aligned.m8n8.x4.trans.shared.b16 {%0,%1,%2,%3}, [%4];" \
                 : "=r"(r0), "=r"(r1), "=r"(r2), "=r"(r3) : "r"(addr))

#define MMA_F16(d, a, b)                                                      \
    asm volatile("mma.sync.aligned.m16n8k16.row.col.f32.f16.f16.f32 "         \
                 "{%0,%1,%2,%3}, {%4,%5,%6,%7}, {%8,%9}, {%0,%1,%2,%3};"      \
                 : "+f"((d)[0]), "+f"((d)[1]), "+f"((d)[2]), "+f"((d)[3])     \
                 : "r"((a)[0]), "r"((a)[1]), "r"((a)[2]), "r"((a)[3]),        \
                   "r"((b)[0]), "r"((b)[1]))

__device__ __forceinline__ uint32_t pack_f16(float lo, float hi) {
    uint32_t r;
    asm("cvt.rn.f16x2.f32 %0, %1, %2;" : "=r"(r) : "f"(hi), "f"(lo));
    return r;
}
__device__ __forceinline__ float2 unpack_f16(uint32_t v) {
    __half2 h = *reinterpret_cast<__half2*>(&v);
    return __half22float2(h);
}

// ---------------------------------------------------------------------------
// conversions
// ---------------------------------------------------------------------------
__global__ void cvt_split_f16(const float* __restrict__ src,
                              __half* __restrict__ hi,
                              __half* __restrict__ lo, int n4) {
    int i = blockIdx.x * blockDim.x + threadIdx.x;
    if (i >= n4) return;
    float4 v = ((const float4*)src)[i];
    uint32_t h01 = pack_f16(v.x, v.y);
    uint32_t h23 = pack_f16(v.z, v.w);
    float2 b01 = unpack_f16(h01);
    float2 b23 = unpack_f16(h23);
    uint32_t l01 = pack_f16(v.x - b01.x, v.y - b01.y);
    uint32_t l23 = pack_f16(v.z - b23.x, v.w - b23.y);
    ((uint2*)hi)[i] = make_uint2(h01, h23);
    ((uint2*)lo)[i] = make_uint2(l01, l23);
}

__global__ void cvt_f16(const float* __restrict__ src,
                        __half* __restrict__ dst, int n4) {
    int i = blockIdx.x * blockDim.x + threadIdx.x;
    if (i >= n4) return;
    float4 v = ((const float4*)src)[i];
    ((uint2*)dst)[i] = make_uint2(pack_f16(v.x, v.y), pack_f16(v.z, v.w));
}

// ---------------------------------------------------------------------------
// mma.sync fp16 GEMM, 2-term A-split: C = (Ah + Al) * Bh^T
// CTA tile 256x128, BK=32, 8 warps (4m x 2n), warp tile 64x64.
// 4-stage cp.async ring, ONE __syncthreads per iteration.
// MODE 0: fp32 C out (out-projection).
// MODE 3: fused QKV. B is [3*EMB, EMB] (Nn=6144). Region by n0:
//         [0,2048) Q -> RoPE, write qh+ql; [2048,4096) K -> RoPE, write kh;
//         [4096,6144) V -> write vh.
// ---------------------------------------------------------------------------
#define GA_TILE (256 * 80)                    // 20480 B
#define GB_TILE (128 * 80)                    // 10240 B
#define G_STAGE (2 * GA_TILE + GB_TILE)       // 51200 B
#define GEMM_SMEM (4 * G_STAGE)               // 204800 B

template <int MODE>
__global__ __launch_bounds__(256, 1)
void gemm_f16(const __half* __restrict__ Ah, const __half* __restrict__ Al,
              const __half* __restrict__ Bh,
              float* __restrict__ C,
              __half* __restrict__ Qh, __half* __restrict__ Ql,
              __half* __restrict__ Kh, __half* __restrict__ Vh,
              const float* __restrict__ cosv, const float* __restrict__ sinv,
              int Kn) {
    extern __shared__ char smem[];
    const uint32_t sb = smem_u32(smem);

    const int tid = threadIdx.x;
    const int lane = tid & 31;
    const int wid = tid >> 5;
    const int wm = wid >> 1;
    const int wn = wid & 1;
    const int m0 = blockIdx.y * 256;
    const int n0 = blockIdx.x * 128;
    const int NS = Kn / 32;

    int arow[4], acc_[4];
    uint32_t asoff[4];
#pragma unroll
    for (int i = 0; i < 4; i++) {
        int c = tid + i * 256;
        arow[i] = c >> 2; acc_[i] = c & 3;
        asoff[i] = arow[i] * 80 + acc_[i] * 16;
    }
    int brow[2], bcc[2];
    uint32_t bsoff[2];
#pragma unroll
    for (int i = 0; i < 2; i++) {
        int c = tid + i * 256;
        brow[i] = c >> 2; bcc[i] = c & 3;
        bsoff[i] = brow[i] * 80 + bcc[i] * 16;
    }

#define LOAD_STAGE(j)                                                         \
    do {                                                                      \
        const uint32_t _b = sb + ((j) & 3) * G_STAGE;                         \
        const int _kg = (j) * 32;                                             \
        _Pragma("unroll")                                                     \
        for (int i = 0; i < 4; i++) {                                         \
            size_t off = (size_t)(m0 + arow[i]) * Kn + _kg + acc_[i] * 8;     \
            CP16(_b + asoff[i],           Ah + off);                          \
            CP16(_b + GA_TILE + asoff[i], Al + off);                          \
        }                                                                     \
        _Pragma("unroll")                                                     \
        for (int i = 0; i < 2; i++) {                                         \
            size_t off = (size_t)(n0 + brow[i]) * Kn + _kg + bcc[i] * 8;      \
            CP16(_b + 2 * GA_TILE + bsoff[i], Bh + off);                      \
        }                                                                     \
        CP_COMMIT();                                                          \
    } while (0)

    const uint32_t aoff = (uint32_t)((wm * 64 + (lane & 15)) * 80 + (lane >> 4) * 16);
    const uint32_t boff = (uint32_t)((wn * 64 + (lane >> 4) * 8 + (lane & 7)) * 80 +
                                     ((lane >> 3) & 1) * 16);

    float acc[4][8][4];
#pragma unroll
    for (int mt = 0; mt < 4; mt++)
#pragma unroll
        for (int nt = 0; nt < 8; nt++)
#pragma unroll
            for (int q = 0; q < 4; q++) acc[mt][nt][q] = 0.f;

    LOAD_STAGE(0);
    LOAD_STAGE(1);
    LOAD_STAGE(2);

    for (int i = 0; i < NS; i++) {
        if (i + 2 < NS)      { CP_WAIT(2); }
        else if (i + 1 < NS) { CP_WAIT(1); }
        else                 { CP_WAIT(0); }
        __syncthreads();
        if (i + 3 < NS) LOAD_STAGE(i + 3);

        const uint32_t base = sb + (i & 3) * G_STAGE;
        const uint32_t sAh = base + aoff;
        const uint32_t sAl = base + GA_TILE + aoff;
        const uint32_t sBh = base + 2 * GA_TILE + boff;

#pragma unroll
        for (int k0 = 0; k0 < 2; k0++) {
            const uint32_t kb = k0 * 32;
            uint32_t ah[4][4], al[4][4];
#pragma unroll
            for (int mt = 0; mt < 4; mt++) {
                LDM_X4(ah[mt][0], ah[mt][1], ah[mt][2], ah[mt][3],
                       sAh + mt * (16 * 80) + kb);
                LDM_X4(al[mt][0], al[mt][1], al[mt][2], al[mt][3],
                       sAl + mt * (16 * 80) + kb);
            }
#pragma unroll
            for (int half = 0; half < 2; half++) {
                uint32_t bh[4][2];
#pragma unroll
                for (int j = 0; j < 2; j++) {
                    uint32_t r0, r1, r2, r3;
                    LDM_X4(r0, r1, r2, r3,
                           sBh + (half * 2 + j) * (16 * 80) + kb);
                    bh[j * 2][0] = r0; bh[j * 2][1] = r1;
                    bh[j * 2 + 1][0] = r2; bh[j * 2 + 1][1] = r3;
                }
#pragma unroll
                for (int mt = 0; mt < 4; mt++)
#pragma unroll
                    for (int ntl = 0; ntl < 4; ntl++) {
                        float* d = acc[mt][half * 4 + ntl];
                        MMA_F16(d, ah[mt], bh[ntl]);
                        MMA_F16(d, al[mt], bh[ntl]);
                    }
            }
        }
    }
#undef LOAD_STAGE

    // ---- epilogue
    const int region = (MODE == 3) ? (n0 >> 11) : 0;   // 0:Q 1:K 2:V
#pragma unroll
    for (int mt = 0; mt < 4; mt++) {
        const int row = m0 + wm * 64 + mt * 16 + (lane >> 2);
#pragma unroll
        for (int nt = 0; nt < 8; nt++) {
            const int col = n0 + wn * 64 + nt * 8 + (lane & 3) * 2;
            float f0 = acc[mt][nt][0], f1 = acc[mt][nt][1];
            float f2 = acc[mt][nt][2], f3 = acc[mt][nt][3];
            if (MODE == 0) {
                *(float2*)&C[(size_t)row * EMB_ + col] = make_float2(f0, f1);
                *(float2*)&C[(size_t)(row + 8) * EMB_ + col] = make_float2(f2, f3);
            } else {
                const int lc = col & (EMB_ - 1);
                if (region < 2) {   // RoPE for Q and K
                    const int i2 = (lc & 127) >> 1;
                    const int t0r = row & (T_ - 1);
                    const int t1r = (row + 8) & (T_ - 1);
                    float c0 = cosv[t0r * 64 + i2], s0 = sinv[t0r * 64 + i2];
                    float c1 = cosv[t1r * 64 + i2], s1 = sinv[t1r * 64 + i2];
                    float r0 = f0 * c0 - f1 * s0, r1 = f0 * s0 + f1 * c0;
                    float r2 = f2 * c1 - f3 * s1, r3 = f2 * s1 + f3 * c1;
                    f0 = r0; f1 = r1; f2 = r2; f3 = r3;
                }
                uint32_t h01 = pack_f16(f0, f1);
                uint32_t h23 = pack_f16(f2, f3);
                const size_t o0 = (size_t)row * EMB_ + lc;
                const size_t o1 = (size_t)(row + 8) * EMB_ + lc;
                if (region == 0) {
                    *(uint32_t*)(Qh + o0) = h01;
                    *(uint32_t*)(Qh + o1) = h23;
                    float2 b01 = unpack_f16(h01);
                    float2 b23 = unpack_f16(h23);
                    *(uint32_t*)(Ql + o0) = pack_f16(f0 - b01.x, f1 - b01.y);
                    *(uint32_t*)(Ql + o1) = pack_f16(f2 - b23.x, f3 - b23.y);
                } else if (region == 1) {
                    *(uint32_t*)(Kh + o0) = h01;
                    *(uint32_t*)(Kh + o1) = h23;
                } else {
                    *(uint32_t*)(Vh + o0) = h01;
                    *(uint32_t*)(Vh + o1) = h23;
                }
            }
        }
    }
}

// ---------------------------------------------------------------------------
// Tensor-core flash attention, fp16 2-term. 4-stage ring, ONE sync per iter.
// ---------------------------------------------------------------------------
#define AT_QB     34816
#define AT_KVT    17408
#define AT_STAGEB (2 * AT_KVT)
#define ATTN_SMEM (2 * AT_QB + 4 * AT_STAGEB)

__global__ __launch_bounds__(256, 1)
void attn_f16(const __half* __restrict__ qh, const __half* __restrict__ ql,
              const __half* __restrict__ kh, const __half* __restrict__ vh,
              __half* __restrict__ oh, __half* __restrict__ ol) {
    extern __shared__ char smem[];
    const uint32_t sb = smem_u32(smem);
    const int tid = threadIdx.x;
    const int lane = tid & 31;
    const int wid = tid >> 5;
    const int qt0 = blockIdx.x * 128;
    const int h = blockIdx.y;
    const int b = blockIdx.z;
    const int bT = b * T_;
    const size_t headcol = (size_t)h * HD_;

    // Q tiles (hi + lo) — committed with stage 0's group
#pragma unroll
    for (int it = 0; it < 8; it++) {
        int x = tid + it * 256;
        int row = x >> 4, c = x & 15;
        size_t g = (size_t)(bT + qt0 + row) * EMB_ + headcol + c * 8;
        CP16(sb + row * 272 + c * 16, qh + g);
        CP16(sb + AT_QB + row * 272 + c * 16, ql + g);
    }

#define AT_STAGE(j)                                                            \
    do {                                                                       \
        const uint32_t bs_ = sb + 2 * AT_QB + ((j) & 3) * AT_STAGEB;           \
        const int kt_ = (j) * 64;                                              \
        _Pragma("unroll")                                                      \
        for (int it = 0; it < 8; it++) {                                       \
            int x = tid + it * 256;                                            \
            int tsel = x >> 10;                                                \
            int w = x & 1023;                                                  \
            int row = w >> 4, c = w & 15;                                      \
            size_t g = (size_t)(bT + kt_ + row) * EMB_ + headcol + c * 8;      \
            const __half* p = (tsel == 0) ? kh : vh;                           \
            CP16(bs_ + tsel * AT_KVT + row * 272 + c * 16, p + g);             \
        }                                                                      \
        CP_COMMIT();                                                           \
    } while (0)

    AT_STAGE(0);
    AT_STAGE(1);
    AT_STAGE(2);

    const uint32_t aoff = (uint32_t)((wid * 16 + (lane & 15)) * 272 + (lane >> 4) * 16);
    const uint32_t koff = (uint32_t)(((lane >> 4) * 8 + (lane & 7)) * 272 +
                                     ((lane >> 3) & 1) * 16);
    const uint32_t voff = (uint32_t)((((lane >> 3) & 1) * 8 + (lane & 7)) * 272 +
                                     (lane >> 4) * 16);

    float acc_o[16][4];
#pragma unroll
    for (int nt = 0; nt < 16; nt++)
#pragma unroll
        for (int q = 0; q < 4; q++) acc_o[nt][q] = 0.f;
    float m0 = -CUDART_INF_F, m1 = -CUDART_INF_F;
    float l0 = 0.f, l1 = 0.f;
    const float sc = 0.08838834764831845f;   // 1/sqrt(128)

    const int NT = T_ / 64;
    for (int it = 0; it < NT; it++) {
        if (it + 2 < NT)      { CP_WAIT(2); }
        else if (it + 1 < NT) { CP_WAIT(1); }
        else                  { CP_WAIT(0); }
        __syncthreads();
        if (it + 3 < NT) AT_STAGE(it + 3);

        const uint32_t bs = sb + 2 * AT_QB + (it & 3) * AT_STAGEB;

        float accs[8][4];
#pragma unroll
        for (int nt = 0; nt < 8; nt++)
#pragma unroll
            for (int q = 0; q < 4; q++) accs[nt][q] = 0.f;

#pragma unroll
        for (int ks = 0; ks < 8; ks++) {
            uint32_t aH[4], aL[4];
            LDM_X4(aH[0], aH[1], aH[2], aH[3], sb + aoff + ks * 32);
            LDM_X4(aL[0], aL[1], aL[2], aL[3], sb + AT_QB + aoff + ks * 32);
#pragma unroll
            for (int jn = 0; jn < 4; jn++) {
                uint32_t r0, r1, r2, r3;
                uint32_t bH[2][2];
                LDM_X4(r0, r1, r2, r3, bs + jn * (16 * 272) + koff + ks * 32);
                bH[0][0] = r0; bH[0][1] = r1; bH[1][0] = r2; bH[1][1] = r3;
#pragma unroll
                for (int q = 0; q < 2; q++) {
                    MMA_F16(accs[jn * 2 + q], aH, bH[q]);
                    MMA_F16(accs[jn * 2 + q], aL, bH[q]);
                }
            }
        }

#pragma unroll
        for (int nt = 0; nt < 8; nt++) {
            accs[nt][0] *= sc; accs[nt][1] *= sc;
            accs[nt][2] *= sc; accs[nt][3] *= sc;
        }

        float rm0 = accs[0][0], rm1 = accs[0][2];
#pragma unroll
        for (int nt = 0; nt < 8; nt++) {
            rm0 = fmaxf(rm0, fmaxf(accs[nt][0], accs[nt][1]));
            rm1 = fmaxf(rm1, fmaxf(accs[nt][2], accs[nt][3]));
        }
        rm0 = fmaxf(rm0, __shfl_xor_sync(0xffffffffu, rm0, 1));
        rm0 = fmaxf(rm0, __shfl_xor_sync(0xffffffffu, rm0, 2));
        rm1 = fmaxf(rm1, __shfl_xor_sync(0xffffffffu, rm1, 1));
        rm1 = fmaxf(rm1, __shfl_xor_sync(0xffffffffu, rm1, 2));

        float mn0 = fmaxf(m0, rm0);
        float mn1 = fmaxf(m1, rm1);
        float al0 = __expf(m0 - mn0);
        float al1 = __expf(m1 - mn1);
        m0 = mn0; m1 = mn1;

        float rs0 = 0.f, rs1 = 0.f;
#pragma unroll
        for (int nt = 0; nt < 8; nt++) {
            accs[nt][0] = __expf(accs[nt][0] - m0);
            accs[nt][1] = __expf(accs[nt][1] - m0);
            accs[nt][2] = __expf(accs[nt][2] - m1);
            accs[nt][3] = __expf(accs[nt][3] - m1);
            rs0 += accs[nt][0] + accs[nt][1];
            rs1 += accs[nt][2] + accs[nt][3];
        }
        rs0 += __shfl_xor_sync(0xffffffffu, rs0, 1);
        rs0 += __shfl_xor_sync(0xffffffffu, rs0, 2);
        rs1 += __shfl_xor_sync(0xffffffffu, rs1, 1);
        rs1 += __shfl_xor_sync(0xffffffffu, rs1, 2);
        l0 = l0 * al0 + rs0;
        l1 = l1 * al1 + rs1;

#pragma unroll
        for (int nt = 0; nt < 16; nt++) {
            acc_o[nt][0] *= al0;
            acc_o[nt][1] *= al0;
            acc_o[nt][2] *= al1;
            acc_o[nt][3] *= al1;
        }

        uint32_t aPh[4][4], aPl[4][4];
#pragma unroll
        for (int ks2 = 0; ks2 < 4; ks2++) {
#pragma unroll
            for (int half = 0; half < 2; half++) {
                int nt = ks2 * 2 + half;
                uint32_t h01 = pack_f16(accs[nt][0], accs[nt][1]);
                uint32_t h23 = pack_f16(accs[nt][2], accs[nt][3]);
                float2 b01 = unpack_f16(h01);
                float2 b23 = unpack_f16(h23);
                uint32_t l01 = pack_f16(accs[nt][0] - b01.x, accs[nt][1] - b01.y);
                uint32_t l23 = pack_f16(accs[nt][2] - b23.x, accs[nt][3] - b23.y);
                aPh[ks2][half * 2]     = h01;
                aPh[ks2][half * 2 + 1] = h23;
                aPl[ks2][half * 2]     = l01;
                aPl[ks2][half * 2 + 1] = l23;
            }
        }

        const uint32_t vb = bs + AT_KVT + voff;
#pragma unroll
        for (int ks2 = 0; ks2 < 4; ks2++) {
#pragma unroll
            for (int j = 0; j < 8; j++) {
                uint32_t r0, r1, r2, r3;
                uint32_t bv[2][2];
                LDM_X4T(r0, r1, r2, r3, vb + ks2 * (16 * 272) + j * 32);
                bv[0][0] = r0; bv[0][1] = r1; bv[1][0] = r2; bv[1][1] = r3;
#pragma unroll
                for (int q = 0; q < 2; q++) {
                    MMA_F16(acc_o[j * 2 + q], aPh[ks2], bv[q]);
                    MMA_F16(acc_o[j * 2 + q], aPl[ks2], bv[q]);
                }
            }
        }
    }
#undef AT_STAGE

    const float inv0 = 1.f / l0;
    const float inv1 = 1.f / l1;
    const size_t gr0 = (size_t)(bT + qt0 + wid * 16 + (lane >> 2)) * EMB_ +
                       headcol + (lane & 3) * 2;
    const size_t gr1 = gr0 + 8 * EMB_;
#pragma unroll
    for (int nt = 0; nt < 16; nt++) {
        float f0 = acc_o[nt][0] * inv0, f1 = acc_o[nt][1] * inv0;
        float f2 = acc_o[nt][2] * inv1, f3 = acc_o[nt][3] * inv1;
        uint32_t h01 = pack_f16(f0, f1);
        uint32_t h23 = pack_f16(f2, f3);
        float2 b01 = unpack_f16(h01);
        float2 b23 = unpack_f16(h23);
        uint32_t l01 = pack_f16(f0 - b01.x, f1 - b01.y);
        uint32_t l23 = pack_f16(f2 - b23.x, f3 - b23.y);
        *(uint32_t*)(oh + gr0 + nt * 8) = h01;
        *(uint32_t*)(ol + gr0 + nt * 8) = l01;
        *(uint32_t*)(oh + gr1 + nt * 8) = h23;
        *(uint32_t*)(ol + gr1 + nt * 8) = l23;
    }
}

// ---------------------------------------------------------------------------
extern "C" void kernel_launch(void* const* d_in, const int* in_sizes, int n_in,
                              void* d_out, int out_size) {
    const float* x    = (const float*)d_in[0];
    const float* wq   = (const float*)d_in[1];
    const float* wk   = (const float*)d_in[2];
    const float* wv   = (const float*)d_in[3];
    const float* wo   = (const float*)d_in[4];
    const float* fcos = (const float*)d_in[7];
    const float* fsin = (const float*)d_in[8];
    float* out = (float*)d_out;

    __half *gxh, *gxl, *gwh, *gah, *gal, *gqh, *gql, *gkh, *gvh;
    cudaGetSymbolAddress((void**)&gxh, g_xh);
    cudaGetSymbolAddress((void**)&gxl, g_xl);
    cudaGetSymbolAddress((void**)&gwh, g_wh);
    cudaGetSymbolAddress((void**)&gah, g_ah);
    cudaGetSymbolAddress((void**)&gal, g_al);
    cudaGetSymbolAddress((void**)&gqh, g_qh);
    cudaGetSymbolAddress((void**)&gql, g_ql);
    cudaGetSymbolAddress((void**)&gkh, g_kh);
    cudaGetSymbolAddress((void**)&gvh, g_vh);

    cudaFuncSetAttribute(gemm_f16<0>,
                         cudaFuncAttributeMaxDynamicSharedMemorySize, GEMM_SMEM);
    cudaFuncSetAttribute(gemm_f16<3>,
                         cudaFuncAttributeMaxDynamicSharedMemorySize, GEMM_SMEM);
    cudaFuncSetAttribute(attn_f16,
                         cudaFuncAttributeMaxDynamicSharedMemorySize, ATTN_SMEM);

    const size_t WSZ = (size_t)EMB_ * EMB_;
    const int n4x = (M_ * EMB_) / 4;
    const int n4w = (EMB_ * EMB_) / 4;

    cvt_split_f16<<<(n4x + 255) / 256, 256>>>(x, gxh, gxl, n4x);
    cvt_f16<<<(n4w + 255) / 256, 256>>>(wq, gwh + 0 * WSZ, n4w);
    cvt_f16<<<(n4w + 255) / 256, 256>>>(wk, gwh + 1 * WSZ, n4w);
    cvt_f16<<<(n4w + 255) / 256, 256>>>(wv, gwh + 2 * WSZ, n4w);
    cvt_f16<<<(n4w + 255) / 256, 256>>>(wo, gwh + 3 * WSZ, n4w);

    // fused QKV projection: N = 3*EMB, one launch, 768 CTAs
    dim3 qkvgrid((3 * EMB_) / 128, M_ / 256);
    gemm_f16<3><<<qkvgrid, 256, GEMM_SMEM>>>(gxh, gxl, gwh,
                                             nullptr, gqh, gql, gkh, gvh,
                                             fcos, fsin, EMB_);

    dim3 agrid(T_ / 128, H_, B_);
    attn_f16<<<agrid, 256, ATTN_SMEM>>>(gqh, gql, gkh, gvh, gah, gal);

    // out projection: fp32 output
    dim3 ogrid(EMB_ / 128, M_ / 256);
    gemm_f16<0><<<ogrid, 256, GEMM_SMEM>>>(gah, gal, gwh + 3 * WSZ,
                                           out, nullptr, nullptr, nullptr, nullptr,
                                           nullptr, nullptr, EMB_);
}

// round 15
// speedup vs baseline: 4.6431x; 1.0812x over previous
#include <cuda_runtime.h>
#include <cuda_fp16.h>
#include <math_constants.h>
#include <cstdint>

#define B_   2
#define T_   2048
#define EMB_ 2048
#define H_   16
#define HD_  128
#define M_   (B_ * T_)   // 4096

// ---------------------------------------------------------------------------
// Scratch (__device__ globals; no allocation allowed)
// ---------------------------------------------------------------------------
__device__ __half g_xh[(size_t)M_ * EMB_];
__device__ __half g_xl[(size_t)M_ * EMB_];
__device__ __half g_wh[4][(size_t)EMB_ * EMB_];   // slots 0,1,2 contiguous = fused QKV weight
__device__ __half g_ah[(size_t)M_ * EMB_];
__device__ __half g_qh[(size_t)M_ * EMB_];
__device__ __half g_ql[(size_t)M_ * EMB_];
__device__ __half g_kh[(size_t)M_ * EMB_];
__device__ __half g_vh[(size_t)M_ * EMB_];

// ---------------------------------------------------------------------------
// helpers
// ---------------------------------------------------------------------------
__device__ __forceinline__ uint32_t smem_u32(const void* p) {
    uint32_t a;
    asm("{ .reg .u64 t; cvta.to.shared.u64 t, %1; cvt.u32.u64 %0, t; }"
        : "=r"(a) : "l"(p));
    return a;
}
#define CP16(dst, src) \
    asm volatile("cp.async.cg.shared.global [%0], [%1], 16;" \
                 :: "r"(dst), "l"(src))
#define CP_COMMIT() asm volatile("cp.async.commit_group;" ::: "memory")
#define CP_WAIT(n)  asm volatile("cp.async.wait_group %0;" :: "n"(n) : "memory")

#define LDM_X4(r0, r1, r2, r3, addr)                                          \
    asm volatile("ldmatrix.sync.aligned.m8n8.x4.shared.b16 {%0,%1,%2,%3}, [%4];" \
                 : "=r"(r0), "=r"(r1), "=r"(r2), "=r"(r3) : "r"(addr))

#define LDM_X4T(r0, r1, r2, r3, addr)                                         \
    asm volatile("ldmatrix.sync.aligned.m8n8.x4.trans.shared.b16 {%0,%1,%2,%3}, [%4];" \
                 : "=r"(r0), "=r"(r1), "=r"(r2), "=r"(r3) : "r"(addr))

#define MMA_F16(d, a, b)                                                      \
    asm volatile("mma.sync.aligned.m16n8k16.row.col.f32.f16.f16.f32 "         \
                 "{%0,%1,%2,%3}, {%4,%5,%6,%7}, {%8,%9}, {%0,%1,%2,%3};"      \
                 : "+f"((d)[0]), "+f"((d)[1]), "+f"((d)[2]), "+f"((d)[3])     \
                 : "r"((a)[0]), "r"((a)[1]), "r"((a)[2]), "r"((a)[3]),        \
                   "r"((b)[0]), "r"((b)[1]))

__device__ __forceinline__ uint32_t pack_f16(float lo, float hi) {
    uint32_t r;
    asm("cvt.rn.f16x2.f32 %0, %1, %2;" : "=r"(r) : "f"(hi), "f"(lo));
    return r;
}
__device__ __forceinline__ float2 unpack_f16(uint32_t v) {
    __half2 h = *reinterpret_cast<__half2*>(&v);
    return __half22float2(h);
}

// ---------------------------------------------------------------------------
// conversions (4 float4 per thread, stride-coalesced)
// ---------------------------------------------------------------------------
__global__ void cvt_split_f16(const float* __restrict__ src,
                              __half* __restrict__ hi,
                              __half* __restrict__ lo) {
    int base = blockIdx.x * 1024 + threadIdx.x;
#pragma unroll
    for (int k = 0; k < 4; k++) {
        int i = base + k * 256;
        float4 v = ((const float4*)src)[i];
        uint32_t h01 = pack_f16(v.x, v.y);
        uint32_t h23 = pack_f16(v.z, v.w);
        float2 b01 = unpack_f16(h01);
        float2 b23 = unpack_f16(h23);
        uint32_t l01 = pack_f16(v.x - b01.x, v.y - b01.y);
        uint32_t l23 = pack_f16(v.z - b23.x, v.w - b23.y);
        ((uint2*)hi)[i] = make_uint2(h01, h23);
        ((uint2*)lo)[i] = make_uint2(l01, l23);
    }
}

__global__ void cvt_w4(const float* __restrict__ w0, const float* __restrict__ w1,
                       const float* __restrict__ w2, const float* __restrict__ w3,
                       __half* __restrict__ dst) {
    const float* src = (blockIdx.y == 0) ? w0 : (blockIdx.y == 1) ? w1
                     : (blockIdx.y == 2) ? w2 : w3;
    __half* d = dst + (size_t)blockIdx.y * EMB_ * EMB_;
    int base = blockIdx.x * 1024 + threadIdx.x;
#pragma unroll
    for (int k = 0; k < 4; k++) {
        int i = base + k * 256;
        float4 v = ((const float4*)src)[i];
        ((uint2*)d)[i] = make_uint2(pack_f16(v.x, v.y), pack_f16(v.z, v.w));
    }
}

// ---------------------------------------------------------------------------
// mma.sync fp16 GEMM: C = (Ah [+ Al]) * Bh^T   (TERMS = 1 or 2)
// CTA tile 256x128, BK=32, 8 warps (4m x 2n), warp tile 64x64.
// 4-stage cp.async ring, one __syncthreads per iteration.
// MODE 0: fp32 C out.  MODE 3: fused QKV epilogue (RoPE for Q/K regions).
// ---------------------------------------------------------------------------
#define GA_TILE (256 * 80)                    // 20480 B
#define GB_TILE (128 * 80)                    // 10240 B

template <int MODE, int TERMS>
__global__ __launch_bounds__(256, 1)
void gemm_f16(const __half* __restrict__ Ah, const __half* __restrict__ Al,
              const __half* __restrict__ Bh,
              float* __restrict__ C,
              __half* __restrict__ Qh, __half* __restrict__ Ql,
              __half* __restrict__ Kh, __half* __restrict__ Vh,
              const float* __restrict__ cosv, const float* __restrict__ sinv,
              int Kn) {
    constexpr uint32_t STAGE = TERMS * GA_TILE + GB_TILE;
    constexpr uint32_t BOFF  = TERMS * GA_TILE;
    extern __shared__ char smem[];
    const uint32_t sb = smem_u32(smem);

    const int tid = threadIdx.x;
    const int lane = tid & 31;
    const int wid = tid >> 5;
    const int wm = wid >> 1;
    const int wn = wid & 1;
    const int m0 = blockIdx.y * 256;
    const int n0 = blockIdx.x * 128;
    const int NS = Kn / 32;

    int arow[4], acc_[4];
    uint32_t asoff[4];
#pragma unroll
    for (int i = 0; i < 4; i++) {
        int c = tid + i * 256;
        arow[i] = c >> 2; acc_[i] = c & 3;
        asoff[i] = arow[i] * 80 + acc_[i] * 16;
    }
    int brow[2], bcc[2];
    uint32_t bsoff[2];
#pragma unroll
    for (int i = 0; i < 2; i++) {
        int c = tid + i * 256;
        brow[i] = c >> 2; bcc[i] = c & 3;
        bsoff[i] = brow[i] * 80 + bcc[i] * 16;
    }

#define LOAD_STAGE(j)                                                         \
    do {                                                                      \
        const uint32_t _b = sb + ((j) & 3) * STAGE;                           \
        const int _kg = (j) * 32;                                             \
        _Pragma("unroll")                                                     \
        for (int i = 0; i < 4; i++) {                                         \
            size_t off = (size_t)(m0 + arow[i]) * Kn + _kg + acc_[i] * 8;     \
            CP16(_b + asoff[i], Ah + off);                                    \
            if (TERMS == 2) CP16(_b + GA_TILE + asoff[i], Al + off);          \
        }                                                                     \
        _Pragma("unroll")                                                     \
        for (int i = 0; i < 2; i++) {                                         \
            size_t off = (size_t)(n0 + brow[i]) * Kn + _kg + bcc[i] * 8;      \
            CP16(_b + BOFF + bsoff[i], Bh + off);                             \
        }                                                                     \
        CP_COMMIT();                                                          \
    } while (0)

    const uint32_t aoff = (uint32_t)((wm * 64 + (lane & 15)) * 80 + (lane >> 4) * 16);
    const uint32_t boff = (uint32_t)((wn * 64 + (lane >> 4) * 8 + (lane & 7)) * 80 +
                                     ((lane >> 3) & 1) * 16);

    float acc[4][8][4];
#pragma unroll
    for (int mt = 0; mt < 4; mt++)
#pragma unroll
        for (int nt = 0; nt < 8; nt++)
#pragma unroll
            for (int q = 0; q < 4; q++) acc[mt][nt][q] = 0.f;

    LOAD_STAGE(0);
    LOAD_STAGE(1);
    LOAD_STAGE(2);

    for (int i = 0; i < NS; i++) {
        if (i + 2 < NS)      { CP_WAIT(2); }
        else if (i + 1 < NS) { CP_WAIT(1); }
        else                 { CP_WAIT(0); }
        __syncthreads();
        if (i + 3 < NS) LOAD_STAGE(i + 3);

        const uint32_t base = sb + (i & 3) * STAGE;
        const uint32_t sAh = base + aoff;
        const uint32_t sAl = base + GA_TILE + aoff;
        const uint32_t sBh = base + BOFF + boff;

#pragma unroll
        for (int k0 = 0; k0 < 2; k0++) {
            const uint32_t kb = k0 * 32;
            uint32_t ah[4][4], al[4][4];
#pragma unroll
            for (int mt = 0; mt < 4; mt++) {
                LDM_X4(ah[mt][0], ah[mt][1], ah[mt][2], ah[mt][3],
                       sAh + mt * (16 * 80) + kb);
                if (TERMS == 2)
                    LDM_X4(al[mt][0], al[mt][1], al[mt][2], al[mt][3],
                           sAl + mt * (16 * 80) + kb);
            }
#pragma unroll
            for (int half = 0; half < 2; half++) {
                uint32_t bh[4][2];
#pragma unroll
                for (int j = 0; j < 2; j++) {
                    uint32_t r0, r1, r2, r3;
                    LDM_X4(r0, r1, r2, r3,
                           sBh + (half * 2 + j) * (16 * 80) + kb);
                    bh[j * 2][0] = r0; bh[j * 2][1] = r1;
                    bh[j * 2 + 1][0] = r2; bh[j * 2 + 1][1] = r3;
                }
#pragma unroll
                for (int mt = 0; mt < 4; mt++)
#pragma unroll
                    for (int ntl = 0; ntl < 4; ntl++) {
                        float* d = acc[mt][half * 4 + ntl];
                        MMA_F16(d, ah[mt], bh[ntl]);
                        if (TERMS == 2) MMA_F16(d, al[mt], bh[ntl]);
                    }
            }
        }
    }
#undef LOAD_STAGE

    // ---- epilogue
    const int region = (MODE == 3) ? (n0 >> 11) : 0;   // 0:Q 1:K 2:V
#pragma unroll
    for (int mt = 0; mt < 4; mt++) {
        const int row = m0 + wm * 64 + mt * 16 + (lane >> 2);
#pragma unroll
        for (int nt = 0; nt < 8; nt++) {
            const int col = n0 + wn * 64 + nt * 8 + (lane & 3) * 2;
            float f0 = acc[mt][nt][0], f1 = acc[mt][nt][1];
            float f2 = acc[mt][nt][2], f3 = acc[mt][nt][3];
            if (MODE == 0) {
                *(float2*)&C[(size_t)row * EMB_ + col] = make_float2(f0, f1);
                *(float2*)&C[(size_t)(row + 8) * EMB_ + col] = make_float2(f2, f3);
            } else {
                const int lc = col & (EMB_ - 1);
                if (region < 2) {   // RoPE for Q and K
                    const int i2 = (lc & 127) >> 1;
                    const int t0r = row & (T_ - 1);
                    const int t1r = (row + 8) & (T_ - 1);
                    float c0 = cosv[t0r * 64 + i2], s0 = sinv[t0r * 64 + i2];
                    float c1 = cosv[t1r * 64 + i2], s1 = sinv[t1r * 64 + i2];
                    float r0 = f0 * c0 - f1 * s0, r1 = f0 * s0 + f1 * c0;
                    float r2 = f2 * c1 - f3 * s1, r3 = f2 * s1 + f3 * c1;
                    f0 = r0; f1 = r1; f2 = r2; f3 = r3;
                }
                uint32_t h01 = pack_f16(f0, f1);
                uint32_t h23 = pack_f16(f2, f3);
                const size_t o0 = (size_t)row * EMB_ + lc;
                const size_t o1 = (size_t)(row + 8) * EMB_ + lc;
                if (region == 0) {
                    *(uint32_t*)(Qh + o0) = h01;
                    *(uint32_t*)(Qh + o1) = h23;
                    float2 b01 = unpack_f16(h01);
                    float2 b23 = unpack_f16(h23);
                    *(uint32_t*)(Ql + o0) = pack_f16(f0 - b01.x, f1 - b01.y);
                    *(uint32_t*)(Ql + o1) = pack_f16(f2 - b23.x, f3 - b23.y);
                } else if (region == 1) {
                    *(uint32_t*)(Kh + o0) = h01;
                    *(uint32_t*)(Kh + o1) = h23;
                } else {
                    *(uint32_t*)(Vh + o0) = h01;
                    *(uint32_t*)(Vh + o1) = h23;
                }
            }
        }
    }
}

// ---------------------------------------------------------------------------
// Tensor-core flash attention, fp16 2-term. 4-stage ring, one sync per iter.
// Output: fp16 hi only (feeds 1-term out-projection).
// ---------------------------------------------------------------------------
#define AT_QB     34816
#define AT_KVT    17408
#define AT_STAGEB (2 * AT_KVT)
#define ATTN_SMEM (2 * AT_QB + 4 * AT_STAGEB)

__global__ __launch_bounds__(256, 1)
void attn_f16(const __half* __restrict__ qh, const __half* __restrict__ ql,
              const __half* __restrict__ kh, const __half* __restrict__ vh,
              __half* __restrict__ oh) {
    extern __shared__ char smem[];
    const uint32_t sb = smem_u32(smem);
    const int tid = threadIdx.x;
    const int lane = tid & 31;
    const int wid = tid >> 5;
    const int qt0 = blockIdx.x * 128;
    const int h = blockIdx.y;
    const int b = blockIdx.z;
    const int bT = b * T_;
    const size_t headcol = (size_t)h * HD_;

#pragma unroll
    for (int it = 0; it < 8; it++) {
        int x = tid + it * 256;
        int row = x >> 4, c = x & 15;
        size_t g = (size_t)(bT + qt0 + row) * EMB_ + headcol + c * 8;
        CP16(sb + row * 272 + c * 16, qh + g);
        CP16(sb + AT_QB + row * 272 + c * 16, ql + g);
    }

#define AT_STAGE(j)                                                            \
    do {                                                                       \
        const uint32_t bs_ = sb + 2 * AT_QB + ((j) & 3) * AT_STAGEB;           \
        const int kt_ = (j) * 64;                                              \
        _Pragma("unroll")                                                      \
        for (int it = 0; it < 8; it++) {                                       \
            int x = tid + it * 256;                                            \
            int tsel = x >> 10;                                                \
            int w = x & 1023;                                                  \
            int row = w >> 4, c = w & 15;                                      \
            size_t g = (size_t)(bT + kt_ + row) * EMB_ + headcol + c * 8;      \
            const __half* p = (tsel == 0) ? kh : vh;                           \
            CP16(bs_ + tsel * AT_KVT + row * 272 + c * 16, p + g);             \
        }                                                                      \
        CP_COMMIT();                                                           \
    } while (0)

    AT_STAGE(0);
    AT_STAGE(1);
    AT_STAGE(2);

    const uint32_t aoff = (uint32_t)((wid * 16 + (lane & 15)) * 272 + (lane >> 4) * 16);
    const uint32_t koff = (uint32_t)(((lane >> 4) * 8 + (lane & 7)) * 272 +
                                     ((lane >> 3) & 1) * 16);
    const uint32_t voff = (uint32_t)((((lane >> 3) & 1) * 8 + (lane & 7)) * 272 +
                                     (lane >> 4) * 16);

    float acc_o[16][4];
#pragma unroll
    for (int nt = 0; nt < 16; nt++)
#pragma unroll
        for (int q = 0; q < 4; q++) acc_o[nt][q] = 0.f;
    float m0 = -CUDART_INF_F, m1 = -CUDART_INF_F;
    float l0 = 0.f, l1 = 0.f;
    const float sc = 0.08838834764831845f;   // 1/sqrt(128)

    const int NT = T_ / 64;
    for (int it = 0; it < NT; it++) {
        if (it + 2 < NT)      { CP_WAIT(2); }
        else if (it + 1 < NT) { CP_WAIT(1); }
        else                  { CP_WAIT(0); }
        __syncthreads();
        if (it + 3 < NT) AT_STAGE(it + 3);

        const uint32_t bs = sb + 2 * AT_QB + (it & 3) * AT_STAGEB;

        float accs[8][4];
#pragma unroll
        for (int nt = 0; nt < 8; nt++)
#pragma unroll
            for (int q = 0; q < 4; q++) accs[nt][q] = 0.f;

#pragma unroll
        for (int ks = 0; ks < 8; ks++) {
            uint32_t aH[4], aL[4];
            LDM_X4(aH[0], aH[1], aH[2], aH[3], sb + aoff + ks * 32);
            LDM_X4(aL[0], aL[1], aL[2], aL[3], sb + AT_QB + aoff + ks * 32);
#pragma unroll
            for (int jn = 0; jn < 4; jn++) {
                uint32_t r0, r1, r2, r3;
                uint32_t bH[2][2];
                LDM_X4(r0, r1, r2, r3, bs + jn * (16 * 272) + koff + ks * 32);
                bH[0][0] = r0; bH[0][1] = r1; bH[1][0] = r2; bH[1][1] = r3;
#pragma unroll
                for (int q = 0; q < 2; q++) {
                    MMA_F16(accs[jn * 2 + q], aH, bH[q]);
                    MMA_F16(accs[jn * 2 + q], aL, bH[q]);
                }
            }
        }

#pragma unroll
        for (int nt = 0; nt < 8; nt++) {
            accs[nt][0] *= sc; accs[nt][1] *= sc;
            accs[nt][2] *= sc; accs[nt][3] *= sc;
        }

        float rm0 = accs[0][0], rm1 = accs[0][2];
#pragma unroll
        for (int nt = 0; nt < 8; nt++) {
            rm0 = fmaxf(rm0, fmaxf(accs[nt][0], accs[nt][1]));
            rm1 = fmaxf(rm1, fmaxf(accs[nt][2], accs[nt][3]));
        }
        rm0 = fmaxf(rm0, __shfl_xor_sync(0xffffffffu, rm0, 1));
        rm0 = fmaxf(rm0, __shfl_xor_sync(0xffffffffu, rm0, 2));
        rm1 = fmaxf(rm1, __shfl_xor_sync(0xffffffffu, rm1, 1));
        rm1 = fmaxf(rm1, __shfl_xor_sync(0xffffffffu, rm1, 2));

        float mn0 = fmaxf(m0, rm0);
        float mn1 = fmaxf(m1, rm1);
        float al0 = __expf(m0 - mn0);
        float al1 = __expf(m1 - mn1);
        m0 = mn0; m1 = mn1;

        float rs0 = 0.f, rs1 = 0.f;
#pragma unroll
        for (int nt = 0; nt < 8; nt++) {
            accs[nt][0] = __expf(accs[nt][0] - m0);
            accs[nt][1] = __expf(accs[nt][1] - m0);
            accs[nt][2] = __expf(accs[nt][2] - m1);
            accs[nt][3] = __expf(accs[nt][3] - m1);
            rs0 += accs[nt][0] + accs[nt][1];
            rs1 += accs[nt][2] + accs[nt][3];
        }
        rs0 += __shfl_xor_sync(0xffffffffu, rs0, 1);
        rs0 += __shfl_xor_sync(0xffffffffu, rs0, 2);
        rs1 += __shfl_xor_sync(0xffffffffu, rs1, 1);
        rs1 += __shfl_xor_sync(0xffffffffu, rs1, 2);
        l0 = l0 * al0 + rs0;
        l1 = l1 * al1 + rs1;

#pragma unroll
        for (int nt = 0; nt < 16; nt++) {
            acc_o[nt][0] *= al0;
            acc_o[nt][1] *= al0;
            acc_o[nt][2] *= al1;
            acc_o[nt][3] *= al1;
        }

        uint32_t aPh[4][4], aPl[4][4];
#pragma unroll
        for (int ks2 = 0; ks2 < 4; ks2++) {
#pragma unroll
            for (int half = 0; half < 2; half++) {
                int nt = ks2 * 2 + half;
                uint32_t h01 = pack_f16(accs[nt][0], accs[nt][1]);
                uint32_t h23 = pack_f16(accs[nt][2], accs[nt][3]);
                float2 b01 = unpack_f16(h01);
                float2 b23 = unpack_f16(h23);
                uint32_t l01 = pack_f16(accs[nt][0] - b01.x, accs[nt][1] - b01.y);
                uint32_t l23 = pack_f16(accs[nt][2] - b23.x, accs[nt][3] - b23.y);
                aPh[ks2][half * 2]     = h01;
                aPh[ks2][half * 2 + 1] = h23;
                aPl[ks2][half * 2]     = l01;
                aPl[ks2][half * 2 + 1] = l23;
            }
        }

        const uint32_t vb = bs + AT_KVT + voff;
#pragma unroll
        for (int ks2 = 0; ks2 < 4; ks2++) {
#pragma unroll
            for (int j = 0; j < 8; j++) {
                uint32_t r0, r1, r2, r3;
                uint32_t bv[2][2];
                LDM_X4T(r0, r1, r2, r3, vb + ks2 * (16 * 272) + j * 32);
                bv[0][0] = r0; bv[0][1] = r1; bv[1][0] = r2; bv[1][1] = r3;
#pragma unroll
                for (int q = 0; q < 2; q++) {
                    MMA_F16(acc_o[j * 2 + q], aPh[ks2], bv[q]);
                    MMA_F16(acc_o[j * 2 + q], aPl[ks2], bv[q]);
                }
            }
        }
    }
#undef AT_STAGE

    const float inv0 = 1.f / l0;
    const float inv1 = 1.f / l1;
    const size_t gr0 = (size_t)(bT + qt0 + wid * 16 + (lane >> 2)) * EMB_ +
                       headcol + (lane & 3) * 2;
    const size_t gr1 = gr0 + 8 * EMB_;
#pragma unroll
    for (int nt = 0; nt < 16; nt++) {
        float f0 = acc_o[nt][0] * inv0, f1 = acc_o[nt][1] * inv0;
        float f2 = acc_o[nt][2] * inv1, f3 = acc_o[nt][3] * inv1;
        *(uint32_t*)(oh + gr0 + nt * 8) = pack_f16(f0, f1);
        *(uint32_t*)(oh + gr1 + nt * 8) = pack_f16(f2, f3);
    }
}

// ---------------------------------------------------------------------------
extern "C" void kernel_launch(void* const* d_in, const int* in_sizes, int n_in,
                              void* d_out, int out_size) {
    const float* x    = (const float*)d_in[0];
    const float* wq   = (const float*)d_in[1];
    const float* wk   = (const float*)d_in[2];
    const float* wv   = (const float*)d_in[3];
    const float* wo   = (const float*)d_in[4];
    const float* fcos = (const float*)d_in[7];
    const float* fsin = (const float*)d_in[8];
    float* out = (float*)d_out;

    __half *gxh, *gxl, *gwh, *gah, *gqh, *gql, *gkh, *gvh;
    cudaGetSymbolAddress((void**)&gxh, g_xh);
    cudaGetSymbolAddress((void**)&gxl, g_xl);
    cudaGetSymbolAddress((void**)&gwh, g_wh);
    cudaGetSymbolAddress((void**)&gah, g_ah);
    cudaGetSymbolAddress((void**)&gqh, g_qh);
    cudaGetSymbolAddress((void**)&gql, g_ql);
    cudaGetSymbolAddress((void**)&gkh, g_kh);
    cudaGetSymbolAddress((void**)&gvh, g_vh);

    const int QKV_SMEM = 4 * (2 * GA_TILE + GB_TILE);   // 204800
    const int O_SMEM   = 4 * (GA_TILE + GB_TILE);       // 122880

    cudaFuncSetAttribute((gemm_f16<3, 2>),
                         cudaFuncAttributeMaxDynamicSharedMemorySize, QKV_SMEM);
    cudaFuncSetAttribute((gemm_f16<0, 1>),
                         cudaFuncAttributeMaxDynamicSharedMemorySize, O_SMEM);
    cudaFuncSetAttribute(attn_f16,
                         cudaFuncAttributeMaxDynamicSharedMemorySize, ATTN_SMEM);

    const size_t WSZ = (size_t)EMB_ * EMB_;

    // conversions: x split (2048 blocks) + all 4 weights in one launch
    cvt_split_f16<<<(M_ * EMB_) / 4096, 256>>>(x, gxh, gxl);
    dim3 wgrid((EMB_ * EMB_) / 4096, 4);
    cvt_w4<<<wgrid, 256>>>(wq, wk, wv, wo, gwh);

    // fused QKV projection: N = 3*EMB, 768 CTAs
    dim3 qkvgrid((3 * EMB_) / 128, M_ / 256);
    gemm_f16<3, 2><<<qkvgrid, 256, QKV_SMEM>>>(gxh, gxl, gwh,
                                               nullptr, gqh, gql, gkh, gvh,
                                               fcos, fsin, EMB_);

    dim3 agrid(T_ / 128, H_, B_);
    attn_f16<<<agrid, 256, ATTN_SMEM>>>(gqh, gql, gkh, gvh, gah);

    // out projection: 1-term fp16 A, fp32 output
    dim3 ogrid(EMB_ / 128, M_ / 256);
    gemm_f16<0, 1><<<ogrid, 256, O_SMEM>>>(gah, nullptr, gwh + 3 * WSZ,
                                           out, nullptr, nullptr, nullptr, nullptr,
                                           nullptr, nullptr, EMB_);
}

// round 17
// speedup vs baseline: 4.8313x; 1.0405x over previous
#include <cuda_runtime.h>
#include <cuda_fp16.h>
#include <math_constants.h>
#include <cstdint>

#define B_   2
#define T_   2048
#define EMB_ 2048
#define H_   16
#define HD_  128
#define M_   (B_ * T_)   // 4096

// ---------------------------------------------------------------------------
// Scratch (__device__ globals; no allocation allowed)
// ---------------------------------------------------------------------------
__device__ __half g_xh[(size_t)M_ * EMB_];
__device__ __half g_xl[(size_t)M_ * EMB_];
__device__ __half g_wh[4][(size_t)EMB_ * EMB_];   // slots 0,1,2 contiguous = fused QKV weight
__device__ __half g_ah[(size_t)M_ * EMB_];
__device__ __half g_qh[(size_t)M_ * EMB_];
__device__ __half g_ql[(size_t)M_ * EMB_];
__device__ __half g_kh[(size_t)M_ * EMB_];
__device__ __half g_vh[(size_t)M_ * EMB_];

// ---------------------------------------------------------------------------
// helpers
// ---------------------------------------------------------------------------
__device__ __forceinline__ uint32_t smem_u32(const void* p) {
    uint32_t a;
    asm("{ .reg .u64 t; cvta.to.shared.u64 t, %1; cvt.u32.u64 %0, t; }"
        : "=r"(a) : "l"(p));
    return a;
}
#define CP16(dst, src) \
    asm volatile("cp.async.cg.shared.global [%0], [%1], 16;" \
                 :: "r"(dst), "l"(src))
#define CP_COMMIT() asm volatile("cp.async.commit_group;" ::: "memory")
#define CP_WAIT(n)  asm volatile("cp.async.wait_group %0;" :: "n"(n) : "memory")

#define LDM_X4(r0, r1, r2, r3, addr)                                          \
    asm volatile("ldmatrix.sync.aligned.m8n8.x4.shared.b16 {%0,%1,%2,%3}, [%4];" \
                 : "=r"(r0), "=r"(r1), "=r"(r2), "=r"(r3) : "r"(addr))

#define LDM_X4T(r0, r1, r2, r3, addr)                                         \
    asm volatile("ldmatrix.sync.aligned.m8n8.x4.trans.shared.b16 {%0,%1,%2,%3}, [%4];" \
                 : "=r"(r0), "=r"(r1), "=r"(r2), "=r"(r3) : "r"(addr))

#define MMA_F16(d, a, b)                                                      \
    asm volatile("mma.sync.aligned.m16n8k16.row.col.f32.f16.f16.f32 "         \
                 "{%0,%1,%2,%3}, {%4,%5,%6,%7}, {%8,%9}, {%0,%1,%2,%3};"      \
                 : "+f"((d)[0]), "+f"((d)[1]), "+f"((d)[2]), "+f"((d)[3])     \
                 : "r"((a)[0]), "r"((a)[1]), "r"((a)[2]), "r"((a)[3]),        \
                   "r"((b)[0]), "r"((b)[1]))

__device__ __forceinline__ uint32_t pack_f16(float lo, float hi) {
    uint32_t r;
    asm("cvt.rn.f16x2.f32 %0, %1, %2;" : "=r"(r) : "f"(hi), "f"(lo));
    return r;
}
__device__ __forceinline__ float2 unpack_f16(uint32_t v) {
    __half2 h = *reinterpret_cast<__half2*>(&v);
    return __half22float2(h);
}

// ---------------------------------------------------------------------------
// conversions (4 float4 per thread, stride-coalesced)
// ---------------------------------------------------------------------------
__global__ void cvt_split_f16(const float* __restrict__ src,
                              __half* __restrict__ hi,
                              __half* __restrict__ lo) {
    int base = blockIdx.x * 1024 + threadIdx.x;
#pragma unroll
    for (int k = 0; k < 4; k++) {
        int i = base + k * 256;
        float4 v = ((const float4*)src)[i];
        uint32_t h01 = pack_f16(v.x, v.y);
        uint32_t h23 = pack_f16(v.z, v.w);
        float2 b01 = unpack_f16(h01);
        float2 b23 = unpack_f16(h23);
        uint32_t l01 = pack_f16(v.x - b01.x, v.y - b01.y);
        uint32_t l23 = pack_f16(v.z - b23.x, v.w - b23.y);
        ((uint2*)hi)[i] = make_uint2(h01, h23);
        ((uint2*)lo)[i] = make_uint2(l01, l23);
    }
}

__global__ void cvt_w4(const float* __restrict__ w0, const float* __restrict__ w1,
                       const float* __restrict__ w2, const float* __restrict__ w3,
                       __half* __restrict__ dst) {
    const float* src = (blockIdx.y == 0) ? w0 : (blockIdx.y == 1) ? w1
                     : (blockIdx.y == 2) ? w2 : w3;
    __half* d = dst + (size_t)blockIdx.y * EMB_ * EMB_;
    int base = blockIdx.x * 1024 + threadIdx.x;
#pragma unroll
    for (int k = 0; k < 4; k++) {
        int i = base + k * 256;
        float4 v = ((const float4*)src)[i];
        ((uint2*)d)[i] = make_uint2(pack_f16(v.x, v.y), pack_f16(v.z, v.w));
    }
}

// ---------------------------------------------------------------------------
// mma.sync fp16 GEMM: C = (Ah [+ Al]) * Bh^T   (TERMS = 1 or 2)
// CTA tile 256x128, BK=32, 8 warps (4m x 2n), warp tile 64x64.
// 4-stage cp.async ring, one __syncthreads per iteration.
// MODE 0: fp32 C out.  MODE 3: fused QKV epilogue (RoPE for Q/K regions).
// ---------------------------------------------------------------------------
#define GA_TILE (256 * 80)                    // 20480 B
#define GB_TILE (128 * 80)                    // 10240 B

template <int MODE, int TERMS>
__global__ __launch_bounds__(256, 1)
void gemm_f16(const __half* __restrict__ Ah, const __half* __restrict__ Al,
              const __half* __restrict__ Bh,
              float* __restrict__ C,
              __half* __restrict__ Qh, __half* __restrict__ Ql,
              __half* __restrict__ Kh, __half* __restrict__ Vh,
              const float* __restrict__ cosv, const float* __restrict__ sinv,
              int Kn) {
    constexpr uint32_t STAGE = TERMS * GA_TILE + GB_TILE;
    constexpr uint32_t BOFF  = TERMS * GA_TILE;
    extern __shared__ char smem[];
    const uint32_t sb = smem_u32(smem);

    const int tid = threadIdx.x;
    const int lane = tid & 31;
    const int wid = tid >> 5;
    const int wm = wid >> 1;
    const int wn = wid & 1;
    const int m0 = blockIdx.y * 256;
    const int n0 = blockIdx.x * 128;
    const int NS = Kn / 32;

    int arow[4], acc_[4];
    uint32_t asoff[4];
#pragma unroll
    for (int i = 0; i < 4; i++) {
        int c = tid + i * 256;
        arow[i] = c >> 2; acc_[i] = c & 3;
        asoff[i] = arow[i] * 80 + acc_[i] * 16;
    }
    int brow[2], bcc[2];
    uint32_t bsoff[2];
#pragma unroll
    for (int i = 0; i < 2; i++) {
        int c = tid + i * 256;
        brow[i] = c >> 2; bcc[i] = c & 3;
        bsoff[i] = brow[i] * 80 + bcc[i] * 16;
    }

#define LOAD_STAGE(j)                                                         \
    do {                                                                      \
        const uint32_t _b = sb + ((j) & 3) * STAGE;                           \
        const int _kg = (j) * 32;                                             \
        _Pragma("unroll")                                                     \
        for (int i = 0; i < 4; i++) {                                         \
            size_t off = (size_t)(m0 + arow[i]) * Kn + _kg + acc_[i] * 8;     \
            CP16(_b + asoff[i], Ah + off);                                    \
            if (TERMS == 2) CP16(_b + GA_TILE + asoff[i], Al + off);          \
        }                                                                     \
        _Pragma("unroll")                                                     \
        for (int i = 0; i < 2; i++) {                                         \
            size_t off = (size_t)(n0 + brow[i]) * Kn + _kg + bcc[i] * 8;      \
            CP16(_b + BOFF + bsoff[i], Bh + off);                             \
        }                                                                     \
        CP_COMMIT();                                                          \
    } while (0)

    const uint32_t aoff = (uint32_t)((wm * 64 + (lane & 15)) * 80 + (lane >> 4) * 16);
    const uint32_t boff = (uint32_t)((wn * 64 + (lane >> 4) * 8 + (lane & 7)) * 80 +
                                     ((lane >> 3) & 1) * 16);

    float acc[4][8][4];
#pragma unroll
    for (int mt = 0; mt < 4; mt++)
#pragma unroll
        for (int nt = 0; nt < 8; nt++)
#pragma unroll
            for (int q = 0; q < 4; q++) acc[mt][nt][q] = 0.f;

    LOAD_STAGE(0);
    LOAD_STAGE(1);
    LOAD_STAGE(2);

    for (int i = 0; i < NS; i++) {
        if (i + 2 < NS)      { CP_WAIT(2); }
        else if (i + 1 < NS) { CP_WAIT(1); }
        else                 { CP_WAIT(0); }
        __syncthreads();
        if (i + 3 < NS) LOAD_STAGE(i + 3);

        const uint32_t base = sb + (i & 3) * STAGE;
        const uint32_t sAh = base + aoff;
        const uint32_t sAl = base + GA_TILE + aoff;
        const uint32_t sBh = base + BOFF + boff;

#pragma unroll
        for (int k0 = 0; k0 < 2; k0++) {
            const uint32_t kb = k0 * 32;
            uint32_t ah[4][4], al[4][4];
#pragma unroll
            for (int mt = 0; mt < 4; mt++) {
                LDM_X4(ah[mt][0], ah[mt][1], ah[mt][2], ah[mt][3],
                       sAh + mt * (16 * 80) + kb);
                if (TERMS == 2)
                    LDM_X4(al[mt][0], al[mt][1], al[mt][2], al[mt][3],
                           sAl + mt * (16 * 80) + kb);
            }
#pragma unroll
            for (int half = 0; half < 2; half++) {
                uint32_t bh[4][2];
#pragma unroll
                for (int j = 0; j < 2; j++) {
                    uint32_t r0, r1, r2, r3;
                    LDM_X4(r0, r1, r2, r3,
                           sBh + (half * 2 + j) * (16 * 80) + kb);
                    bh[j * 2][0] = r0; bh[j * 2][1] = r1;
                    bh[j * 2 + 1][0] = r2; bh[j * 2 + 1][1] = r3;
                }
#pragma unroll
                for (int mt = 0; mt < 4; mt++)
#pragma unroll
                    for (int ntl = 0; ntl < 4; ntl++) {
                        float* d = acc[mt][half * 4 + ntl];
                        MMA_F16(d, ah[mt], bh[ntl]);
                        if (TERMS == 2) MMA_F16(d, al[mt], bh[ntl]);
                    }
            }
        }
    }
#undef LOAD_STAGE

    // ---- epilogue
    const int region = (MODE == 3) ? (n0 >> 11) : 0;   // 0:Q 1:K 2:V
#pragma unroll
    for (int mt = 0; mt < 4; mt++) {
        const int row = m0 + wm * 64 + mt * 16 + (lane >> 2);
#pragma unroll
        for (int nt = 0; nt < 8; nt++) {
            const int col = n0 + wn * 64 + nt * 8 + (lane & 3) * 2;
            float f0 = acc[mt][nt][0], f1 = acc[mt][nt][1];
            float f2 = acc[mt][nt][2], f3 = acc[mt][nt][3];
            if (MODE == 0) {
                *(float2*)&C[(size_t)row * EMB_ + col] = make_float2(f0, f1);
                *(float2*)&C[(size_t)(row + 8) * EMB_ + col] = make_float2(f2, f3);
            } else {
                const int lc = col & (EMB_ - 1);
                if (region < 2) {   // RoPE for Q and K
                    const int i2 = (lc & 127) >> 1;
                    const int t0r = row & (T_ - 1);
                    const int t1r = (row + 8) & (T_ - 1);
                    float c0 = cosv[t0r * 64 + i2], s0 = sinv[t0r * 64 + i2];
                    float c1 = cosv[t1r * 64 + i2], s1 = sinv[t1r * 64 + i2];
                    float r0 = f0 * c0 - f1 * s0, r1 = f0 * s0 + f1 * c0;
                    float r2 = f2 * c1 - f3 * s1, r3 = f2 * s1 + f3 * c1;
                    f0 = r0; f1 = r1; f2 = r2; f3 = r3;
                }
                uint32_t h01 = pack_f16(f0, f1);
                uint32_t h23 = pack_f16(f2, f3);
                const size_t o0 = (size_t)row * EMB_ + lc;
                const size_t o1 = (size_t)(row + 8) * EMB_ + lc;
                if (region == 0) {
                    *(uint32_t*)(Qh + o0) = h01;
                    *(uint32_t*)(Qh + o1) = h23;
                    float2 b01 = unpack_f16(h01);
                    float2 b23 = unpack_f16(h23);
                    *(uint32_t*)(Ql + o0) = pack_f16(f0 - b01.x, f1 - b01.y);
                    *(uint32_t*)(Ql + o1) = pack_f16(f2 - b23.x, f3 - b23.y);
                } else if (region == 1) {
                    *(uint32_t*)(Kh + o0) = h01;
                    *(uint32_t*)(Kh + o1) = h23;
                } else {
                    *(uint32_t*)(Vh + o0) = h01;
                    *(uint32_t*)(Vh + o1) = h23;
                }
            }
        }
    }
}

// ---------------------------------------------------------------------------
// Tensor-core flash attention v2: 64 q-rows/CTA, 128 threads (4 warps x 16 rows),
// Q held in REGISTERS (loaded once via smem), 3-stage K/V ring, 2 CTAs/SM.
// smem: 3 stages x (Kh+Vh = 2x17408) = 104448 B.
// ---------------------------------------------------------------------------
#define AT_KVT    17408
#define AT_STAGEB (2 * AT_KVT)
#define ATTN_SMEM (3 * AT_STAGEB)

__global__ __launch_bounds__(128, 2)
void attn_f16(const __half* __restrict__ qh, const __half* __restrict__ ql,
              const __half* __restrict__ kh, const __half* __restrict__ vh,
              __half* __restrict__ oh) {
    extern __shared__ char smem[];
    const uint32_t sb = smem_u32(smem);
    const int tid = threadIdx.x;
    const int lane = tid & 31;
    const int wid = tid >> 5;          // 0..3
    const int qt0 = blockIdx.x * 64;
    const int h = blockIdx.y;
    const int b = blockIdx.z;
    const int bT = b * T_;
    const size_t headcol = (size_t)h * HD_;

    // ---- load Q (hi+lo) into stage-0 smem temporarily, convert to fragments
    {
#pragma unroll
        for (int it = 0; it < 8; it++) {
            int x = tid + it * 128;
            int row = x >> 4, c = x & 15;
            size_t g = (size_t)(bT + qt0 + row) * EMB_ + headcol + c * 8;
            CP16(sb + row * 272 + c * 16, qh + g);
            CP16(sb + AT_KVT + row * 272 + c * 16, ql + g);
        }
        CP_COMMIT();
        CP_WAIT(0);
        __syncthreads();
    }

    const uint32_t aoff = (uint32_t)((wid * 16 + (lane & 15)) * 272 + (lane >> 4) * 16);
    uint32_t qH[8][4], qL[8][4];
#pragma unroll
    for (int ks = 0; ks < 8; ks++) {
        LDM_X4(qH[ks][0], qH[ks][1], qH[ks][2], qH[ks][3], sb + aoff + ks * 32);
        LDM_X4(qL[ks][0], qL[ks][1], qL[ks][2], qL[ks][3],
               sb + AT_KVT + aoff + ks * 32);
    }
    __syncthreads();   // Q region free for K/V stage reuse

#define AT_STAGE(j)                                                            \
    do {                                                                       \
        const uint32_t bs_ = sb + ((j) % 3) * AT_STAGEB;                       \
        const int kt_ = (j) * 64;                                              \
        _Pragma("unroll")                                                      \
        for (int it = 0; it < 16; it++) {                                      \
            int x = tid + it * 128;                                            \
            int tsel = x >> 10;                                                \
            int w = x & 1023;                                                  \
            int row = w >> 4, c = w & 15;                                      \
            size_t g = (size_t)(bT + kt_ + row) * EMB_ + headcol + c * 8;      \
            const __half* p = (tsel == 0) ? kh : vh;                           \
            CP16(bs_ + tsel * AT_KVT + row * 272 + c * 16, p + g);             \
        }                                                                      \
        CP_COMMIT();                                                           \
    } while (0)

    AT_STAGE(0);
    AT_STAGE(1);

    const uint32_t koff = (uint32_t)(((lane >> 4) * 8 + (lane & 7)) * 272 +
                                     ((lane >> 3) & 1) * 16);
    const uint32_t voff = (uint32_t)((((lane >> 3) & 1) * 8 + (lane & 7)) * 272 +
                                     (lane >> 4) * 16);

    float acc_o[16][4];
#pragma unroll
    for (int nt = 0; nt < 16; nt++)
#pragma unroll
        for (int q = 0; q < 4; q++) acc_o[nt][q] = 0.f;
    float m0 = -CUDART_INF_F, m1 = -CUDART_INF_F;
    float l0 = 0.f, l1 = 0.f;
    const float sc = 0.08838834764831845f;   // 1/sqrt(128)

    const int NT = T_ / 64;
    for (int it = 0; it < NT; it++) {
        if (it + 1 < NT) { CP_WAIT(1); }
        else             { CP_WAIT(0); }
        __syncthreads();
        if (it + 2 < NT) AT_STAGE(it + 2);

        const uint32_t bs = sb + (it % 3) * AT_STAGEB;

        float accs[8][4];
#pragma unroll
        for (int nt = 0; nt < 8; nt++)
#pragma unroll
            for (int q = 0; q < 4; q++) accs[nt][q] = 0.f;

#pragma unroll
        for (int ks = 0; ks < 8; ks++) {
#pragma unroll
            for (int jn = 0; jn < 4; jn++) {
                uint32_t r0, r1, r2, r3;
                uint32_t bH[2][2];
                LDM_X4(r0, r1, r2, r3, bs + jn * (16 * 272) + koff + ks * 32);
                bH[0][0] = r0; bH[0][1] = r1; bH[1][0] = r2; bH[1][1] = r3;
#pragma unroll
                for (int q = 0; q < 2; q++) {
                    MMA_F16(accs[jn * 2 + q], qH[ks], bH[q]);
                    MMA_F16(accs[jn * 2 + q], qL[ks], bH[q]);
                }
            }
        }

#pragma unroll
        for (int nt = 0; nt < 8; nt++) {
            accs[nt][0] *= sc; accs[nt][1] *= sc;
            accs[nt][2] *= sc; accs[nt][3] *= sc;
        }

        float rm0 = accs[0][0], rm1 = accs[0][2];
#pragma unroll
        for (int nt = 0; nt < 8; nt++) {
            rm0 = fmaxf(rm0, fmaxf(accs[nt][0], accs[nt][1]));
            rm1 = fmaxf(rm1, fmaxf(accs[nt][2], accs[nt][3]));
        }
        rm0 = fmaxf(rm0, __shfl_xor_sync(0xffffffffu, rm0, 1));
        rm0 = fmaxf(rm0, __shfl_xor_sync(0xffffffffu, rm0, 2));
        rm1 = fmaxf(rm1, __shfl_xor_sync(0xffffffffu, rm1, 1));
        rm1 = fmaxf(rm1, __shfl_xor_sync(0xffffffffu, rm1, 2));

        float mn0 = fmaxf(m0, rm0);
        float mn1 = fmaxf(m1, rm1);
        float al0 = __expf(m0 - mn0);
        float al1 = __expf(m1 - mn1);
        m0 = mn0; m1 = mn1;

        float rs0 = 0.f, rs1 = 0.f;
#pragma unroll
        for (int nt = 0; nt < 8; nt++) {
            accs[nt][0] = __expf(accs[nt][0] - m0);
            accs[nt][1] = __expf(accs[nt][1] - m0);
            accs[nt][2] = __expf(accs[nt][2] - m1);
            accs[nt][3] = __expf(accs[nt][3] - m1);
            rs0 += accs[nt][0] + accs[nt][1];
            rs1 += accs[nt][2] + accs[nt][3];
        }
        rs0 += __shfl_xor_sync(0xffffffffu, rs0, 1);
        rs0 += __shfl_xor_sync(0xffffffffu, rs0, 2);
        rs1 += __shfl_xor_sync(0xffffffffu, rs1, 1);
        rs1 += __shfl_xor_sync(0xffffffffu, rs1, 2);
        l0 = l0 * al0 + rs0;
        l1 = l1 * al1 + rs1;

#pragma unroll
        for (int nt = 0; nt < 16; nt++) {
            acc_o[nt][0] *= al0;
            acc_o[nt][1] *= al0;
            acc_o[nt][2] *= al1;
            acc_o[nt][3] *= al1;
        }

        uint32_t aPh[4][4], aPl[4][4];
#pragma unroll
        for (int ks2 = 0; ks2 < 4; ks2++) {
#pragma unroll
            for (int half = 0; half < 2; half++) {
                int nt = ks2 * 2 + half;
                uint32_t h01 = pack_f16(accs[nt][0], accs[nt][1]);
                uint32_t h23 = pack_f16(accs[nt][2], accs[nt][3]);
                float2 b01 = unpack_f16(h01);
                float2 b23 = unpack_f16(h23);
                uint32_t l01 = pack_f16(accs[nt][0] - b01.x, accs[nt][1] - b01.y);
                uint32_t l23 = pack_f16(accs[nt][2] - b23.x, accs[nt][3] - b23.y);
                aPh[ks2][half * 2]     = h01;
                aPh[ks2][half * 2 + 1] = h23;
                aPl[ks2][half * 2]     = l01;
                aPl[ks2][half * 2 + 1] = l23;
            }
        }

        const uint32_t vb = bs + AT_KVT + voff;
#pragma unroll
        for (int ks2 = 0; ks2 < 4; ks2++) {
#pragma unroll
            for (int j = 0; j < 8; j++) {
                uint32_t r0, r1, r2, r3;
                uint32_t bv[2][2];
                LDM_X4T(r0, r1, r2, r3, vb + ks2 * (16 * 272) + j * 32);
                bv[0][0] = r0; bv[0][1] = r1; bv[1][0] = r2; bv[1][1] = r3;
#pragma unroll
                for (int q = 0; q < 2; q++) {
                    MMA_F16(acc_o[j * 2 + q], aPh[ks2], bv[q]);
                    MMA_F16(acc_o[j * 2 + q], aPl[ks2], bv[q]);
                }
            }
        }
    }
#undef AT_STAGE

    const float inv0 = 1.f / l0;
    const float inv1 = 1.f / l1;
    const size_t gr0 = (size_t)(bT + qt0 + wid * 16 + (lane >> 2)) * EMB_ +
                       headcol + (lane & 3) * 2;
    const size_t gr1 = gr0 + 8 * EMB_;
#pragma unroll
    for (int nt = 0; nt < 16; nt++) {
        float f0 = acc_o[nt][0] * inv0, f1 = acc_o[nt][1] * inv0;
        float f2 = acc_o[nt][2] * inv1, f3 = acc_o[nt][3] * inv1;
        *(uint32_t*)(oh + gr0 + nt * 8) = pack_f16(f0, f1);
        *(uint32_t*)(oh + gr1 + nt * 8) = pack_f16(f2, f3);
    }
}

// ---------------------------------------------------------------------------
extern "C" void kernel_launch(void* const* d_in, const int* in_sizes, int n_in,
                              void* d_out, int out_size) {
    const float* x    = (const float*)d_in[0];
    const float* wq   = (const float*)d_in[1];
    const float* wk   = (const float*)d_in[2];
    const float* wv   = (const float*)d_in[3];
    const float* wo   = (const float*)d_in[4];
    const float* fcos = (const float*)d_in[7];
    const float* fsin = (const float*)d_in[8];
    float* out = (float*)d_out;

    __half *gxh, *gxl, *gwh, *gah, *gqh, *gql, *gkh, *gvh;
    cudaGetSymbolAddress((void**)&gxh, g_xh);
    cudaGetSymbolAddress((void**)&gxl, g_xl);
    cudaGetSymbolAddress((void**)&gwh, g_wh);
    cudaGetSymbolAddress((void**)&gah, g_ah);
    cudaGetSymbolAddress((void**)&gqh, g_qh);
    cudaGetSymbolAddress((void**)&gql, g_ql);
    cudaGetSymbolAddress((void**)&gkh, g_kh);
    cudaGetSymbolAddress((void**)&gvh, g_vh);

    const int QKV_SMEM = 4 * (2 * GA_TILE + GB_TILE);   // 204800
    const int O_SMEM   = 4 * (GA_TILE + GB_TILE);       // 122880

    cudaFuncSetAttribute((gemm_f16<3, 2>),
                         cudaFuncAttributeMaxDynamicSharedMemorySize, QKV_SMEM);
    cudaFuncSetAttribute((gemm_f16<0, 1>),
                         cudaFuncAttributeMaxDynamicSharedMemorySize, O_SMEM);
    cudaFuncSetAttribute(attn_f16,
                         cudaFuncAttributeMaxDynamicSharedMemorySize, ATTN_SMEM);

    const size_t WSZ = (size_t)EMB_ * EMB_;

    cvt_split_f16<<<(M_ * EMB_) / 4096, 256>>>(x, gxh, gxl);
    dim3 wgrid((EMB_ * EMB_) / 4096, 4);
    cvt_w4<<<wgrid, 256>>>(wq, wk, wv, wo, gwh);

    // fused QKV projection: N = 3*EMB, 768 CTAs
    dim3 qkvgrid((3 * EMB_) / 128, M_ / 256);
    gemm_f16<3, 2><<<qkvgrid, 256, QKV_SMEM>>>(gxh, gxl, gwh,
                                               nullptr, gqh, gql, gkh, gvh,
                                               fcos, fsin, EMB_);

    dim3 agrid(T_ / 64, H_, B_);
    attn_f16<<<agrid, 128, ATTN_SMEM>>>(gqh, gql, gkh, gvh, gah);

    // out projection: 1-term fp16 A, fp32 output
    dim3 ogrid(EMB_ / 128, M_ / 256);
    gemm_f16<0, 1><<<ogrid, 256, O_SMEM>>>(gah, nullptr, gwh + 3 * WSZ,
                                           out, nullptr, nullptr, nullptr, nullptr,
                                           nullptr, nullptr, EMB_);
}